// round 3
// baseline (speedup 1.0000x reference)
#include <cuda_runtime.h>
#include <math.h>

#define B_WIN 1024
#define SEQ   288
#define CH    96
#define NH    4
#define HD    24
#define NW    128
#define M_ROWS (B_WIN * SEQ)   // 294912

// ---------------- scratch (device globals; no runtime allocation) ----------
__device__ float g_Q[B_WIN * NH * SEQ * HD];   // 113 MB, q pre-scaled
__device__ float g_K[B_WIN * NH * SEQ * HD];
__device__ float g_V[B_WIN * NH * SEQ * HD];
__device__ float g_O[M_ROWS * CH];             // attention output, [b][n][h*24+dd]

// ===========================================================================
// Kernel 1: QKV projection.  grid = M/128, block = 256.
// smem: xs[128][100] (float4-loadable pad) + ws transposed [96(k)][97]
// out tile 128 x 96 per column-chunk (3 chunks: q, k, v); micro-tile 8x6.
// ===========================================================================
__global__ __launch_bounds__(256) void qkv_kernel(
    const float* __restrict__ x,
    const float* __restrict__ qkv_w,
    const float* __restrict__ qkv_b)
{
    extern __shared__ float sm[];
    float* xs = sm;               // [128][100]
    float* ws = sm + 128 * 100;   // [96][97]  ws[k*97 + o] = w[cc+o][k]

    const int tid = threadIdx.x;
    const int m0  = blockIdx.x * 128;

    // load x tile, coalesced float4
    for (int idx = tid; idx < 128 * 24; idx += 256) {
        int r = idx / 24, c4 = idx % 24;
        float4 v = *(const float4*)(x + (size_t)(m0 + r) * 96 + c4 * 4);
        *(float4*)(xs + r * 100 + c4 * 4) = v;
    }

    const int tx = tid & 15;      // 16 col-groups of 6
    const int ty = tid >> 4;      // 16 row-groups of 8
    const float scale = 0.20412414523193154f; // 24^-0.5

    for (int s = 0; s < 3; ++s) {
        const int cc = s * 96;
        __syncthreads();
        // transposed weight chunk (coalesced gmem read, padded smem store)
        for (int idx = tid; idx < 96 * 96; idx += 256) {
            int o = idx / 96, k = idx % 96;
            ws[k * 97 + o] = qkv_w[(size_t)(cc + o) * 96 + k];
        }
        __syncthreads();

        float acc[8][6];
        #pragma unroll
        for (int i = 0; i < 8; i++)
            #pragma unroll
            for (int j = 0; j < 6; j++) acc[i][j] = 0.f;

        #pragma unroll 4
        for (int kk = 0; kk < 96; ++kk) {
            float xr[8], wc[6];
            #pragma unroll
            for (int i = 0; i < 8; i++) xr[i] = xs[(ty * 8 + i) * 100 + kk];
            #pragma unroll
            for (int j = 0; j < 6; j++) wc[j] = ws[kk * 97 + tx * 6 + j];
            #pragma unroll
            for (int i = 0; i < 8; i++)
                #pragma unroll
                for (int j = 0; j < 6; j++) acc[i][j] += xr[i] * wc[j];
        }

        float* dst = (s == 0) ? g_Q : (s == 1) ? g_K : g_V;
        #pragma unroll
        for (int j = 0; j < 6; j++) {
            const int o  = tx * 6 + j;       // 0..95 within chunk
            const int h  = o / 24;
            const int dd = o % 24;
            const float bias = qkv_b[cc + o];
            #pragma unroll
            for (int i = 0; i < 8; i++) {
                const int m = m0 + ty * 8 + i;
                const int b = m / SEQ, n = m % SEQ;
                float val = acc[i][j] + bias;
                if (s == 0) val *= scale;
                dst[(((size_t)b * NH + h) * SEQ + n) * HD + dd] = val;
            }
        }
    }
}

// ===========================================================================
// Kernel 2: fused attention, one block per (b, h).  block = 256.
// smem: Ks[288][25] + Vs[288][25] + Qs[96][25] + S[96][289]  (178 KB)
// 3 query chunks of 96 rows:
//   S = Q K^T  : 9x12 micro-tile over a 32x8 thread grid (96 rows x 288 cols)
//   +mask, exact softmax (warp per row)
//   O = P V    : 3x3 micro-tile over a 32x8 thread grid (96 rows x 24 cols)
// ===========================================================================
__global__ __launch_bounds__(256) void attn_kernel(const float* __restrict__ mask)
{
    extern __shared__ float sm[];
    float* Ks = sm;                         // [288][25]
    float* Vs = Ks + SEQ * 25;              // [288][25]
    float* Qs = Vs + SEQ * 25;              // [96][25]
    float* S  = Qs + 96 * 25;               // [96][289]

    const int tid = threadIdx.x;
    const int bh  = blockIdx.x;
    const int b   = bh >> 2;
    const int h   = bh & 3;
    const int w   = b & (NW - 1);           // b % nW
    const size_t base = (size_t)bh * SEQ * HD;

    for (int idx = tid; idx < SEQ * HD; idx += 256) {
        const int r = idx / HD, c = idx % HD;
        Ks[r * 25 + c] = g_K[base + idx];
        Vs[r * 25 + c] = g_V[base + idx];
    }

    // QK tiling: 96 rows -> 8 groups of 12(cols? no, rows); use:
    //   rows: ty in [0,8)  x 12 rows each? We want 9x12: 96 = 12*8? Choose:
    //   ty = tid >> 5 (8 groups, 12 rows each)  -> 12 rows per thread-group row
    //   tx = tid & 31 (32 groups, 9 cols each)  -> 288 = 32*9
    const int tx = tid & 31, ty = tid >> 5;     // QK: 12 rows x 9 cols per thread
    const int lane = tid & 31, wid = tid >> 5;  // softmax: warp per row
    const int pc = tid & 7, pr = tid >> 3;      // PV tiling: 3 rows x 3 cols

    for (int qc = 0; qc < 3; ++qc) {
        const int n0 = qc * 96;
        __syncthreads();   // K/V (first iter) / previous chunk's PV done
        for (int idx = tid; idx < 96 * HD; idx += 256) {
            const int r = idx / HD, c = idx % HD;
            Qs[r * 25 + c] = g_Q[base + (size_t)n0 * HD + idx];
        }
        __syncthreads();

        // ---- S = Q K^T  (12 rows x 9 cols per thread) -------------------
        {
            float acc[12][9];
            #pragma unroll
            for (int i = 0; i < 12; i++)
                #pragma unroll
                for (int j = 0; j < 9; j++) acc[i][j] = 0.f;

            #pragma unroll
            for (int kk = 0; kk < HD; ++kk) {
                float q12[12], k9[9];
                #pragma unroll
                for (int i = 0; i < 12; i++) q12[i] = Qs[(ty * 12 + i) * 25 + kk];
                #pragma unroll
                for (int j = 0; j < 9; j++)  k9[j]  = Ks[(tx * 9 + j) * 25 + kk];
                #pragma unroll
                for (int i = 0; i < 12; i++)
                    #pragma unroll
                    for (int j = 0; j < 9; j++) acc[i][j] += q12[i] * k9[j];
            }
            #pragma unroll
            for (int i = 0; i < 12; i++)
                #pragma unroll
                for (int j = 0; j < 9; j++)
                    S[(ty * 12 + i) * 289 + tx * 9 + j] = acc[i][j];
        }
        __syncthreads();

        // ---- mask + softmax (one warp per row, 12 rows/warp) -----------
        for (int t = 0; t < 12; ++t) {
            const int row = wid * 12 + t;
            const float* mrow = mask + ((size_t)w * SEQ + (n0 + row)) * SEQ;
            float v[9];
            float mx = -1e30f;
            #pragma unroll
            for (int q2 = 0; q2 < 9; q2++) {
                const int c = lane + 32 * q2;
                v[q2] = S[row * 289 + c] + __ldg(mrow + c);
                mx = fmaxf(mx, v[q2]);
            }
            #pragma unroll
            for (int off = 16; off; off >>= 1)
                mx = fmaxf(mx, __shfl_xor_sync(0xffffffffu, mx, off));
            float ssum = 0.f;
            #pragma unroll
            for (int q2 = 0; q2 < 9; q2++) { v[q2] = __expf(v[q2] - mx); ssum += v[q2]; }
            #pragma unroll
            for (int off = 16; off; off >>= 1)
                ssum += __shfl_xor_sync(0xffffffffu, ssum, off);
            const float inv = 1.f / ssum;
            #pragma unroll
            for (int q2 = 0; q2 < 9; q2++)
                S[row * 289 + lane + 32 * q2] = v[q2] * inv;
        }
        __syncthreads();

        // ---- O = P V ---------------------------------------------------
        {
            float acc2[3][3];
            #pragma unroll
            for (int i = 0; i < 3; i++)
                #pragma unroll
                for (int c = 0; c < 3; c++) acc2[i][c] = 0.f;

            #pragma unroll 4
            for (int j = 0; j < SEQ; ++j) {
                float p3[3], v3[3];
                #pragma unroll
                for (int i = 0; i < 3; i++) p3[i] = S[(pr * 3 + i) * 289 + j];
                #pragma unroll
                for (int c = 0; c < 3; c++) v3[c] = Vs[j * 25 + pc * 3 + c];
                #pragma unroll
                for (int i = 0; i < 3; i++)
                    #pragma unroll
                    for (int c = 0; c < 3; c++) acc2[i][c] += p3[i] * v3[c];
            }
            #pragma unroll
            for (int i = 0; i < 3; i++) {
                const int row = n0 + pr * 3 + i;
                #pragma unroll
                for (int c = 0; c < 3; c++)
                    g_O[((size_t)b * SEQ + row) * CH + h * HD + pc * 3 + c] = acc2[i][c];
            }
        }
    }
}

// ===========================================================================
// Kernel 3: output projection.  grid = M/128, block = 256.  Same GEMM skeleton.
// ===========================================================================
__global__ __launch_bounds__(256) void proj_kernel(
    const float* __restrict__ proj_w,
    const float* __restrict__ proj_b,
    float* __restrict__ out)
{
    extern __shared__ float sm[];
    float* xs = sm;               // [128][100]
    float* ws = sm + 128 * 100;   // [96][97]  ws[k*97 + o] = proj_w[o][k]

    const int tid = threadIdx.x;
    const int m0  = blockIdx.x * 128;

    for (int idx = tid; idx < 128 * 24; idx += 256) {
        int r = idx / 24, c4 = idx % 24;
        float4 v = *(const float4*)(g_O + (size_t)(m0 + r) * 96 + c4 * 4);
        *(float4*)(xs + r * 100 + c4 * 4) = v;
    }
    for (int idx = tid; idx < 96 * 96; idx += 256) {
        int o = idx / 96, k = idx % 96;
        ws[k * 97 + o] = proj_w[(size_t)o * 96 + k];
    }
    __syncthreads();

    const int tx = tid & 15, ty = tid >> 4;
    float acc[8][6];
    #pragma unroll
    for (int i = 0; i < 8; i++)
        #pragma unroll
        for (int j = 0; j < 6; j++) acc[i][j] = 0.f;

    #pragma unroll 4
    for (int kk = 0; kk < 96; ++kk) {
        float xr[8], wc[6];
        #pragma unroll
        for (int i = 0; i < 8; i++) xr[i] = xs[(ty * 8 + i) * 100 + kk];
        #pragma unroll
        for (int j = 0; j < 6; j++) wc[j] = ws[kk * 97 + tx * 6 + j];
        #pragma unroll
        for (int i = 0; i < 8; i++)
            #pragma unroll
            for (int j = 0; j < 6; j++) acc[i][j] += xr[i] * wc[j];
    }

    #pragma unroll
    for (int j = 0; j < 6; j++) {
        const int o = tx * 6 + j;
        const float bias = proj_b[o];
        #pragma unroll
        for (int i = 0; i < 8; i++) {
            const int m = m0 + ty * 8 + i;
            out[(size_t)m * 96 + o] = acc[i][j] + bias;
        }
    }
}

// ===========================================================================
extern "C" void kernel_launch(void* const* d_in, const int* in_sizes, int n_in,
                              void* d_out, int out_size)
{
    const float* x      = (const float*)d_in[0];
    const float* mask   = (const float*)d_in[1];
    const float* qkv_w  = (const float*)d_in[2];
    const float* qkv_b  = (const float*)d_in[3];
    const float* proj_w = (const float*)d_in[4];
    const float* proj_b = (const float*)d_in[5];
    float* out = (float*)d_out;

    const int smem1 = (128 * 100 + 96 * 97) * 4;                       // 88448
    const int smem2 = (SEQ * 25 * 2 + 96 * 25 + 96 * 289) * 4;         // 178176

    cudaFuncSetAttribute(qkv_kernel,  cudaFuncAttributeMaxDynamicSharedMemorySize, smem1);
    cudaFuncSetAttribute(attn_kernel, cudaFuncAttributeMaxDynamicSharedMemorySize, smem2);
    cudaFuncSetAttribute(proj_kernel, cudaFuncAttributeMaxDynamicSharedMemorySize, smem1);

    qkv_kernel<<<M_ROWS / 128, 256, smem1>>>(x, qkv_w, qkv_b);
    attn_kernel<<<B_WIN * NH, 256, smem2>>>(mask);
    proj_kernel<<<M_ROWS / 128, 256, smem1>>>(proj_w, proj_b, out);
}

// round 5
// speedup vs baseline: 1.2013x; 1.2013x over previous
#include <cuda_runtime.h>
#include <math.h>

#define B_WIN 1024
#define SEQ   288
#define CH    96
#define NH    4
#define HD    24
#define NW    128
#define M_ROWS (B_WIN * SEQ)   // 294912

typedef unsigned long long u64;

// ---------------- f32x2 helpers (Blackwell packed fp32) --------------------
__device__ __forceinline__ void fma2(u64& d, u64 a, u64 b) {
    asm("fma.rn.f32x2 %0, %1, %2, %0;" : "+l"(d) : "l"(a), "l"(b));
}
__device__ __forceinline__ u64 dup2(float v) {
    u64 r; asm("mov.b64 %0, {%1, %2};" : "=l"(r) : "f"(v), "f"(v)); return r;
}
__device__ __forceinline__ u64 ld2s(const float* p) {
    float2 v = *(const float2*)p;
    u64 r; asm("mov.b64 %0, {%1, %2};" : "=l"(r) : "f"(v.x), "f"(v.y)); return r;
}
__device__ __forceinline__ float2 unp2(u64 v) {
    float2 f; asm("mov.b64 {%0, %1}, %2;" : "=f"(f.x), "=f"(f.y) : "l"(v)); return f;
}

// ---------------- scratch (device globals; no runtime allocation) ----------
__device__ float g_Q[B_WIN * NH * SEQ * HD];   // q pre-scaled
__device__ float g_K[B_WIN * NH * SEQ * HD];
__device__ float g_V[B_WIN * NH * SEQ * HD];
__device__ float g_O[M_ROWS * CH];

// ===========================================================================
// Kernel 1: QKV projection.  grid = M/128, block = 256, 2 blocks/SM.
// smem: xs[128][100] + ws[96(k)][98]  (88.8 KB)
// micro-tile 8 rows x 6 cols = 8 x 3 f32x2 pairs.
// ===========================================================================
__global__ __launch_bounds__(256, 2) void qkv_kernel(
    const float* __restrict__ x,
    const float* __restrict__ qkv_w,
    const float* __restrict__ qkv_b)
{
    extern __shared__ float sm[];
    float* xs = sm;               // [128][100]
    float* ws = sm + 128 * 100;   // [96][98]  ws[k*98 + o] = w[cc+o][k]

    const int tid = threadIdx.x;
    const int m0  = blockIdx.x * 128;

    for (int idx = tid; idx < 128 * 24; idx += 256) {
        int r = idx / 24, c4 = idx % 24;
        float4 v = *(const float4*)(x + (size_t)(m0 + r) * 96 + c4 * 4);
        *(float4*)(xs + r * 100 + c4 * 4) = v;
    }

    const int tx = tid & 15;      // 16 col-groups of 6 (3 pairs)
    const int ty = tid >> 4;      // 16 row-groups of 8
    const float scale = 0.20412414523193154f; // 24^-0.5

    for (int s = 0; s < 3; ++s) {
        const int cc = s * 96;
        __syncthreads();
        for (int idx = tid; idx < 96 * 96; idx += 256) {
            int o = idx / 96, k = idx % 96;
            ws[k * 98 + o] = qkv_w[(size_t)(cc + o) * 96 + k];
        }
        __syncthreads();

        u64 acc[8][3];
        #pragma unroll
        for (int i = 0; i < 8; i++)
            #pragma unroll
            for (int j = 0; j < 3; j++) acc[i][j] = 0ULL;

        #pragma unroll 4
        for (int kk = 0; kk < 96; ++kk) {
            u64 xd[8], wp[3];
            #pragma unroll
            for (int i = 0; i < 8; i++) xd[i] = dup2(xs[(ty * 8 + i) * 100 + kk]);
            #pragma unroll
            for (int j = 0; j < 3; j++) wp[j] = ld2s(&ws[kk * 98 + tx * 6 + 2 * j]);
            #pragma unroll
            for (int i = 0; i < 8; i++)
                #pragma unroll
                for (int j = 0; j < 3; j++) fma2(acc[i][j], wp[j], xd[i]);
        }

        float* dst = (s == 0) ? g_Q : (s == 1) ? g_K : g_V;
        #pragma unroll
        for (int j = 0; j < 3; j++) {
            const int o  = tx * 6 + 2 * j;   // even -> pair stays inside a head
            const int h  = o / 24;
            const int dd = o % 24;
            const float b0 = qkv_b[cc + o], b1 = qkv_b[cc + o + 1];
            #pragma unroll
            for (int i = 0; i < 8; i++) {
                const int m = m0 + ty * 8 + i;
                const int b = m / SEQ, n = m % SEQ;
                float2 v = unp2(acc[i][j]);
                v.x += b0; v.y += b1;
                if (s == 0) { v.x *= scale; v.y *= scale; }
                *(float2*)(dst + (((size_t)b * NH + h) * SEQ + n) * HD + dd) = v;
            }
        }
    }
}

// ===========================================================================
// Kernel 2: fused attention, one block per (b, h).  block = 256 (8 warps).
// smem: KsT[24][290] + Vs[288][26] + QsT[24][98] + S[96][289] + Pred[96][24]
//       = 187392 B  (1 block/SM)
// 3 query chunks of 96 rows:
//   QK: thread (tx in 0..31 -> 9 cols, ty in 0..7 -> 12 rows = 6 row-pairs)
//       54 f32x2 per kk; q row-pairs contiguous in QsT, k scalar + dup.
//   softmax: warp per row (12 rows/warp), exact, mask from gmem (L2 resident)
//   PV: 2-way K-split; thread tile 3 rows x 6 cols (3x3 f32x2),
//       V col-pairs contiguous in Vs; smem partial reduction.
// ===========================================================================
__global__ __launch_bounds__(256) void attn_kernel(const float* __restrict__ mask)
{
    extern __shared__ float sm[];
    float* KsT  = sm;                       // [24][290]
    float* Vs   = KsT + 24 * 290;           // [288][26]
    float* QsT  = Vs  + SEQ * 26;           // [24][98]
    float* S    = QsT + 24 * 98;            // [96][289]
    float* Pred = S   + 96 * 289;           // [96][24]

    const int tid = threadIdx.x;
    const int bh  = blockIdx.x;
    const int b   = bh >> 2;
    const int h   = bh & 3;
    const int w   = b & (NW - 1);
    const size_t base = (size_t)bh * SEQ * HD;

    for (int idx = tid; idx < SEQ * HD; idx += 256) {
        const int r = idx / HD, c = idx % HD;
        KsT[c * 290 + r] = g_K[base + idx];
        Vs[r * 26 + c]   = g_V[base + idx];
    }

    const int tx = tid & 31, ty = tid >> 5;      // QK: 12 rows x 9 cols
    const int lane = tid & 31, wid = tid >> 5;   // softmax: warp per row
    const int kp = tid >> 7;                     // PV k-split half (0/1)
    const int pr = (tid & 127) >> 2;             // 32 row groups of 3
    const int pc = tid & 3;                      // 4 col groups of 6

    for (int qc = 0; qc < 3; ++qc) {
        const int n0 = qc * 96;
        __syncthreads();
        for (int idx = tid; idx < 96 * HD; idx += 256) {
            const int r = idx / HD, c = idx % HD;
            QsT[c * 98 + r] = g_Q[base + (size_t)n0 * HD + idx];
        }
        __syncthreads();

        // ---- S = Q K^T  (6 row-pairs x 9 cols of f32x2) ----------------
        {
            u64 acc[6][9];
            #pragma unroll
            for (int i = 0; i < 6; i++)
                #pragma unroll
                for (int j = 0; j < 9; j++) acc[i][j] = 0ULL;

            #pragma unroll 2
            for (int kk = 0; kk < HD; ++kk) {
                u64 qp[6], kd[9];
                #pragma unroll
                for (int i = 0; i < 6; i++)
                    qp[i] = ld2s(&QsT[kk * 98 + ty * 12 + 2 * i]);   // broadcast
                #pragma unroll
                for (int j = 0; j < 9; j++)
                    kd[j] = dup2(KsT[kk * 290 + tx * 9 + j]);
                #pragma unroll
                for (int i = 0; i < 6; i++)
                    #pragma unroll
                    for (int j = 0; j < 9; j++) fma2(acc[i][j], qp[i], kd[j]);
            }
            #pragma unroll
            for (int i = 0; i < 6; i++)
                #pragma unroll
                for (int j = 0; j < 9; j++) {
                    float2 v = unp2(acc[i][j]);
                    S[(ty * 12 + 2 * i)     * 289 + tx * 9 + j] = v.x;
                    S[(ty * 12 + 2 * i + 1) * 289 + tx * 9 + j] = v.y;
                }
        }
        __syncthreads();

        // ---- mask + softmax (one warp per row, 12 rows/warp) -----------
        for (int t = 0; t < 12; ++t) {
            const int row = wid * 12 + t;
            const float* mrow = mask + ((size_t)w * SEQ + (n0 + row)) * SEQ;
            float v[9];
            float mx = -1e30f;
            #pragma unroll
            for (int q2 = 0; q2 < 9; q2++) {
                const int c = lane + 32 * q2;
                v[q2] = S[row * 289 + c] + __ldg(mrow + c);
                mx = fmaxf(mx, v[q2]);
            }
            #pragma unroll
            for (int off = 16; off; off >>= 1)
                mx = fmaxf(mx, __shfl_xor_sync(0xffffffffu, mx, off));
            float ssum = 0.f;
            #pragma unroll
            for (int q2 = 0; q2 < 9; q2++) { v[q2] = __expf(v[q2] - mx); ssum += v[q2]; }
            #pragma unroll
            for (int off = 16; off; off >>= 1)
                ssum += __shfl_xor_sync(0xffffffffu, ssum, off);
            const float inv = 1.f / ssum;
            #pragma unroll
            for (int q2 = 0; q2 < 9; q2++)
                S[row * 289 + lane + 32 * q2] = v[q2] * inv;
        }
        __syncthreads();

        // ---- O = P V  (3 rows x 3 col-pairs, 2-way K-split) ------------
        {
            u64 acc2[3][3];
            #pragma unroll
            for (int i = 0; i < 3; i++)
                #pragma unroll
                for (int c = 0; c < 3; c++) acc2[i][c] = 0ULL;

            const float* Sr0 = S + (pr * 3 + 0) * 289;
            const float* Sr1 = S + (pr * 3 + 1) * 289;
            const float* Sr2 = S + (pr * 3 + 2) * 289;
            const int j0 = kp * 144;
            #pragma unroll 3
            for (int jj = 0; jj < 144; ++jj) {
                const int j = j0 + jj;
                u64 pd[3], vv[3];
                pd[0] = dup2(Sr0[j]);
                pd[1] = dup2(Sr1[j]);
                pd[2] = dup2(Sr2[j]);
                #pragma unroll
                for (int c = 0; c < 3; c++)
                    vv[c] = ld2s(&Vs[j * 26 + pc * 6 + 2 * c]);
                #pragma unroll
                for (int i = 0; i < 3; i++)
                    #pragma unroll
                    for (int c = 0; c < 3; c++) fma2(acc2[i][c], vv[c], pd[i]);
            }

            if (kp == 1) {
                #pragma unroll
                for (int i = 0; i < 3; i++)
                    #pragma unroll
                    for (int c = 0; c < 3; c++)
                        *(float2*)&Pred[(pr * 3 + i) * 24 + pc * 6 + 2 * c] =
                            unp2(acc2[i][c]);
            }
            __syncthreads();
            if (kp == 0) {
                #pragma unroll
                for (int i = 0; i < 3; i++) {
                    const int row = n0 + pr * 3 + i;
                    #pragma unroll
                    for (int c = 0; c < 3; c++) {
                        float2 mine = unp2(acc2[i][c]);
                        float2 oth  = *(float2*)&Pred[(pr * 3 + i) * 24 + pc * 6 + 2 * c];
                        float2 o2 = make_float2(mine.x + oth.x, mine.y + oth.y);
                        *(float2*)(g_O + ((size_t)b * SEQ + row) * CH
                                       + h * HD + pc * 6 + 2 * c) = o2;
                    }
                }
            }
        }
    }
}

// ===========================================================================
// Kernel 3: output projection.  grid = M/128, block = 256, 2 blocks/SM.
// ===========================================================================
__global__ __launch_bounds__(256, 2) void proj_kernel(
    const float* __restrict__ proj_w,
    const float* __restrict__ proj_b,
    float* __restrict__ out)
{
    extern __shared__ float sm[];
    float* xs = sm;               // [128][100]
    float* ws = sm + 128 * 100;   // [96][98]

    const int tid = threadIdx.x;
    const int m0  = blockIdx.x * 128;

    for (int idx = tid; idx < 128 * 24; idx += 256) {
        int r = idx / 24, c4 = idx % 24;
        float4 v = *(const float4*)(g_O + (size_t)(m0 + r) * 96 + c4 * 4);
        *(float4*)(xs + r * 100 + c4 * 4) = v;
    }
    for (int idx = tid; idx < 96 * 96; idx += 256) {
        int o = idx / 96, k = idx % 96;
        ws[k * 98 + o] = proj_w[(size_t)o * 96 + k];
    }
    __syncthreads();

    const int tx = tid & 15, ty = tid >> 4;
    u64 acc[8][3];
    #pragma unroll
    for (int i = 0; i < 8; i++)
        #pragma unroll
        for (int j = 0; j < 3; j++) acc[i][j] = 0ULL;

    #pragma unroll 4
    for (int kk = 0; kk < 96; ++kk) {
        u64 xd[8], wp[3];
        #pragma unroll
        for (int i = 0; i < 8; i++) xd[i] = dup2(xs[(ty * 8 + i) * 100 + kk]);
        #pragma unroll
        for (int j = 0; j < 3; j++) wp[j] = ld2s(&ws[kk * 98 + tx * 6 + 2 * j]);
        #pragma unroll
        for (int i = 0; i < 8; i++)
            #pragma unroll
            for (int j = 0; j < 3; j++) fma2(acc[i][j], wp[j], xd[i]);
    }

    #pragma unroll
    for (int j = 0; j < 3; j++) {
        const int o = tx * 6 + 2 * j;
        const float b0 = proj_b[o], b1 = proj_b[o + 1];
        #pragma unroll
        for (int i = 0; i < 8; i++) {
            const int m = m0 + ty * 8 + i;
            float2 v = unp2(acc[i][j]);
            *(float2*)(out + (size_t)m * 96 + o) = make_float2(v.x + b0, v.y + b1);
        }
    }
}

// ===========================================================================
extern "C" void kernel_launch(void* const* d_in, const int* in_sizes, int n_in,
                              void* d_out, int out_size)
{
    const float* x      = (const float*)d_in[0];
    const float* mask   = (const float*)d_in[1];
    const float* qkv_w  = (const float*)d_in[2];
    const float* qkv_b  = (const float*)d_in[3];
    const float* proj_w = (const float*)d_in[4];
    const float* proj_b = (const float*)d_in[5];
    float* out = (float*)d_out;

    const int smem1 = (128 * 100 + 96 * 98) * 4;                         // 88832
    const int smem2 = (24 * 290 + SEQ * 26 + 24 * 98 + 96 * 289 + 96 * 24) * 4; // 187392

    cudaFuncSetAttribute(qkv_kernel,  cudaFuncAttributeMaxDynamicSharedMemorySize, smem1);
    cudaFuncSetAttribute(attn_kernel, cudaFuncAttributeMaxDynamicSharedMemorySize, smem2);
    cudaFuncSetAttribute(proj_kernel, cudaFuncAttributeMaxDynamicSharedMemorySize, smem1);

    qkv_kernel<<<M_ROWS / 128, 256, smem1>>>(x, qkv_w, qkv_b);
    attn_kernel<<<B_WIN * NH, 256, smem2>>>(mask);
    proj_kernel<<<M_ROWS / 128, 256, smem1>>>(proj_w, proj_b, out);
}

// round 7
// speedup vs baseline: 1.2342x; 1.0274x over previous
#include <cuda_runtime.h>
#include <math.h>

#define B_WIN 1024
#define SEQ   288
#define CH    96
#define NH    4
#define HD    24
#define NW    128
#define M_ROWS (B_WIN * SEQ)   // 294912
#define SSTR  290              // S row stride (even -> aligned float2 stores)

// ---------------- tf32 mma helpers (sm_80+ legacy path) --------------------
__device__ __forceinline__ unsigned tf32_of(float f) {
    unsigned r; asm("cvt.rna.tf32.f32 %0, %1;" : "=r"(r) : "f"(f)); return r;
}
__device__ __forceinline__ void mma_tf32(float* d, const unsigned* a, const unsigned* b) {
    asm volatile("mma.sync.aligned.m16n8k8.row.col.f32.tf32.tf32.f32 "
        "{%0,%1,%2,%3}, {%4,%5,%6,%7}, {%8,%9}, {%0,%1,%2,%3};"
        : "+f"(d[0]), "+f"(d[1]), "+f"(d[2]), "+f"(d[3])
        : "r"(a[0]), "r"(a[1]), "r"(a[2]), "r"(a[3]), "r"(b[0]), "r"(b[1]));
}

// ---------------- scratch (device globals; no runtime allocation) ----------
__device__ float g_Q[B_WIN * NH * SEQ * HD];   // q pre-scaled
__device__ float g_K[B_WIN * NH * SEQ * HD];
__device__ float g_V[B_WIN * NH * SEQ * HD];
__device__ float g_O[M_ROWS * CH];

// ===========================================================================
// Kernel 1: QKV projection (scalar fp32, at scalar-FFMA roofline).
// grid = M/128, block = 256, 2 blocks/SM.
// ===========================================================================
__global__ __launch_bounds__(256, 2) void qkv_kernel(
    const float* __restrict__ x,
    const float* __restrict__ qkv_w,
    const float* __restrict__ qkv_b)
{
    extern __shared__ float sm[];
    float* xs = sm;               // [128][100]
    float* ws = sm + 128 * 100;   // [96][98]  ws[k*98 + o] = w[cc+o][k]

    const int tid = threadIdx.x;
    const int m0  = blockIdx.x * 128;

    for (int idx = tid; idx < 128 * 24; idx += 256) {
        int r = idx / 24, c4 = idx % 24;
        float4 v = *(const float4*)(x + (size_t)(m0 + r) * 96 + c4 * 4);
        *(float4*)(xs + r * 100 + c4 * 4) = v;
    }

    const int tx = tid & 15;      // 16 col-groups of 6
    const int ty = tid >> 4;      // 16 row-groups of 8
    const float scale = 0.20412414523193154f; // 24^-0.5

    for (int s = 0; s < 3; ++s) {
        const int cc = s * 96;
        __syncthreads();
        for (int idx = tid; idx < 96 * 96; idx += 256) {
            int o = idx / 96, k = idx % 96;
            ws[k * 98 + o] = qkv_w[(size_t)(cc + o) * 96 + k];
        }
        __syncthreads();

        float acc[8][6];
        #pragma unroll
        for (int i = 0; i < 8; i++)
            #pragma unroll
            for (int j = 0; j < 6; j++) acc[i][j] = 0.f;

        #pragma unroll 4
        for (int kk = 0; kk < 96; ++kk) {
            float xr[8], wc[6];
            #pragma unroll
            for (int i = 0; i < 8; i++) xr[i] = xs[(ty * 8 + i) * 100 + kk];
            #pragma unroll
            for (int j = 0; j < 6; j++) wc[j] = ws[kk * 98 + tx * 6 + j];
            #pragma unroll
            for (int i = 0; i < 8; i++)
                #pragma unroll
                for (int j = 0; j < 6; j++) acc[i][j] += xr[i] * wc[j];
        }

        float* dst = (s == 0) ? g_Q : (s == 1) ? g_K : g_V;
        #pragma unroll
        for (int j = 0; j < 6; j++) {
            const int o  = tx * 6 + j;
            const int h  = o / 24;
            const int dd = o % 24;
            const float bias = qkv_b[cc + o];
            #pragma unroll
            for (int i = 0; i < 8; i++) {
                const int m = m0 + ty * 8 + i;
                const int b = m / SEQ, n = m % SEQ;
                float val = acc[i][j] + bias;
                if (s == 0) val *= scale;
                dst[(((size_t)b * NH + h) * SEQ + n) * HD + dd] = val;
            }
        }
    }
}

// ===========================================================================
// Kernel 2: fused attention, one block per (b, h).  block = 256 (8 warps).
// tf32 mma.sync for QK and PV; exact fp32 softmax.
// smem: Ks[288][25] + Vs[288][26] + Qs[96][25] + S[96][290] + Pred[4][96][24]
//     = 216576 B, 1 block/SM.
// QK: warp = 48 rows x 72 cols (3 m-tiles x 9 n-tiles x 3 ksteps).
// PV: 24 units (6 m-tiles x 4 k-quarters), 3 per warp, smem reduction.
// ===========================================================================
__global__ __launch_bounds__(256) void attn_kernel(const float* __restrict__ mask)
{
    extern __shared__ float sm[];
    float* Ks   = sm;                        // [288][25]
    float* Vs   = Ks + SEQ * 25;             // [288][26]
    float* Qs   = Vs + SEQ * 26;             // [96][25]
    float* S    = Qs + 96 * 25;              // [96][290]
    float* Pred = S  + 96 * SSTR;            // [4][96][24]

    const int tid = threadIdx.x;
    const int bh  = blockIdx.x;
    const int b   = bh >> 2;
    const int h   = bh & 3;
    const int w   = b & (NW - 1);
    const size_t base = (size_t)bh * SEQ * HD;

    for (int idx = tid; idx < SEQ * HD; idx += 256) {
        const int r = idx / HD, c = idx % HD;
        Ks[r * 25 + c] = g_K[base + idx];
        Vs[r * 26 + c] = g_V[base + idx];
    }

    const int wq   = tid >> 5;
    const int lane = tid & 31;
    const int gid  = lane >> 2;       // mma groupID (0..7)
    const int t4   = lane & 3;        // mma thread-in-group (0..3)
    const int rowg = wq >> 2;         // QK row group (0..1)
    const int colg = wq & 3;          // QK col group (0..3)

    for (int qc = 0; qc < 3; ++qc) {
        const int n0 = qc * 96;
        __syncthreads();
        for (int idx = tid; idx < 96 * HD; idx += 256) {
            const int r = idx / HD, c = idx % HD;
            Qs[r * 25 + c] = g_Q[base + (size_t)n0 * HD + idx];
        }
        __syncthreads();

        // ---- S = Q K^T  (tf32 mma) -------------------------------------
        {
            unsigned kb[9][3][2];
            #pragma unroll
            for (int nt = 0; nt < 9; nt++) {
                const float* kr = Ks + (colg * 72 + nt * 8 + gid) * 25 + t4;
                #pragma unroll
                for (int ks = 0; ks < 3; ks++) {
                    kb[nt][ks][0] = tf32_of(kr[ks * 8]);
                    kb[nt][ks][1] = tf32_of(kr[ks * 8 + 4]);
                }
            }
            #pragma unroll
            for (int mt = 0; mt < 3; mt++) {
                const int m = rowg * 48 + mt * 16;
                const float* q0 = Qs + (m + gid) * 25 + t4;
                const float* q1 = q0 + 8 * 25;
                unsigned qa[3][4];
                #pragma unroll
                for (int ks = 0; ks < 3; ks++) {
                    qa[ks][0] = tf32_of(q0[ks * 8]);
                    qa[ks][1] = tf32_of(q1[ks * 8]);
                    qa[ks][2] = tf32_of(q0[ks * 8 + 4]);
                    qa[ks][3] = tf32_of(q1[ks * 8 + 4]);
                }
                float acc[9][4];
                #pragma unroll
                for (int nt = 0; nt < 9; nt++)
                    #pragma unroll
                    for (int r = 0; r < 4; r++) acc[nt][r] = 0.f;
                #pragma unroll
                for (int ks = 0; ks < 3; ks++)
                    #pragma unroll
                    for (int nt = 0; nt < 9; nt++)
                        mma_tf32(acc[nt], qa[ks], kb[nt][ks]);

                float* s0 = S + (m + gid) * SSTR;
                float* s1 = s0 + 8 * SSTR;
                #pragma unroll
                for (int nt = 0; nt < 9; nt++) {
                    const int n = colg * 72 + nt * 8 + t4 * 2;
                    *(float2*)(s0 + n) = make_float2(acc[nt][0], acc[nt][1]);
                    *(float2*)(s1 + n) = make_float2(acc[nt][2], acc[nt][3]);
                }
            }
        }
        __syncthreads();

        // ---- mask + softmax (one warp per row, 12 rows/warp) -----------
        for (int t = 0; t < 12; ++t) {
            const int row = wq * 12 + t;
            const float* mrow = mask + ((size_t)w * SEQ + (n0 + row)) * SEQ;
            float v[9];
            float mx = -1e30f;
            #pragma unroll
            for (int q2 = 0; q2 < 9; q2++) {
                const int c = lane + 32 * q2;
                v[q2] = S[row * SSTR + c] + __ldg(mrow + c);
                mx = fmaxf(mx, v[q2]);
            }
            #pragma unroll
            for (int off = 16; off; off >>= 1)
                mx = fmaxf(mx, __shfl_xor_sync(0xffffffffu, mx, off));
            float ssum = 0.f;
            #pragma unroll
            for (int q2 = 0; q2 < 9; q2++) { v[q2] = __expf(v[q2] - mx); ssum += v[q2]; }
            #pragma unroll
            for (int off = 16; off; off >>= 1)
                ssum += __shfl_xor_sync(0xffffffffu, ssum, off);
            const float inv = 1.f / ssum;
            #pragma unroll
            for (int q2 = 0; q2 < 9; q2++)
                S[row * SSTR + lane + 32 * q2] = v[q2] * inv;
        }
        __syncthreads();

        // ---- O = P V  (tf32 mma, 4-way k-split, units balanced) --------
        for (int uu = wq; uu < 24; uu += 8) {
            const int mt = uu >> 2, kq = uu & 3;
            float acc[3][4];
            #pragma unroll
            for (int nt = 0; nt < 3; nt++)
                #pragma unroll
                for (int r = 0; r < 4; r++) acc[nt][r] = 0.f;

            #pragma unroll 3
            for (int ks = 0; ks < 9; ks++) {
                const int k0 = kq * 72 + ks * 8;
                const float* p0 = S + (mt * 16 + gid) * SSTR + k0 + t4;
                const float* p1 = p0 + 8 * SSTR;
                unsigned pa[4];
                pa[0] = tf32_of(p0[0]);
                pa[1] = tf32_of(p1[0]);
                pa[2] = tf32_of(p0[4]);
                pa[3] = tf32_of(p1[4]);
                #pragma unroll
                for (int nt = 0; nt < 3; nt++) {
                    unsigned vb[2];
                    vb[0] = tf32_of(Vs[(k0 + t4) * 26 + nt * 8 + gid]);
                    vb[1] = tf32_of(Vs[(k0 + 4 + t4) * 26 + nt * 8 + gid]);
                    mma_tf32(acc[nt], pa, vb);
                }
            }
            float* pr = Pred + kq * (96 * 24);
            #pragma unroll
            for (int nt = 0; nt < 3; nt++) {
                const int c = nt * 8 + t4 * 2;
                *(float2*)(pr + (mt * 16 + gid) * 24 + c) =
                    make_float2(acc[nt][0], acc[nt][1]);
                *(float2*)(pr + (mt * 16 + 8 + gid) * 24 + c) =
                    make_float2(acc[nt][2], acc[nt][3]);
            }
        }
        __syncthreads();

        // ---- reduce 4 k-quarters, write O ------------------------------
        for (int e = tid; e < 96 * 24; e += 256) {
            const float s = Pred[e] + Pred[e + 2304] + Pred[e + 4608] + Pred[e + 6912];
            const int r = e / 24, c = e % 24;
            g_O[((size_t)b * SEQ + n0 + r) * CH + h * HD + c] = s;
        }
    }
}

// ===========================================================================
// Kernel 3: output projection (scalar fp32).  grid = M/128, block = 256.
// ===========================================================================
__global__ __launch_bounds__(256, 2) void proj_kernel(
    const float* __restrict__ proj_w,
    const float* __restrict__ proj_b,
    float* __restrict__ out)
{
    extern __shared__ float sm[];
    float* xs = sm;               // [128][100]
    float* ws = sm + 128 * 100;   // [96][98]

    const int tid = threadIdx.x;
    const int m0  = blockIdx.x * 128;

    for (int idx = tid; idx < 128 * 24; idx += 256) {
        int r = idx / 24, c4 = idx % 24;
        float4 v = *(const float4*)(g_O + (size_t)(m0 + r) * 96 + c4 * 4);
        *(float4*)(xs + r * 100 + c4 * 4) = v;
    }
    for (int idx = tid; idx < 96 * 96; idx += 256) {
        int o = idx / 96, k = idx % 96;
        ws[k * 98 + o] = proj_w[(size_t)o * 96 + k];
    }
    __syncthreads();

    const int tx = tid & 15, ty = tid >> 4;
    float acc[8][6];
    #pragma unroll
    for (int i = 0; i < 8; i++)
        #pragma unroll
        for (int j = 0; j < 6; j++) acc[i][j] = 0.f;

    #pragma unroll 4
    for (int kk = 0; kk < 96; ++kk) {
        float xr[8], wc[6];
        #pragma unroll
        for (int i = 0; i < 8; i++) xr[i] = xs[(ty * 8 + i) * 100 + kk];
        #pragma unroll
        for (int j = 0; j < 6; j++) wc[j] = ws[kk * 98 + tx * 6 + j];
        #pragma unroll
        for (int i = 0; i < 8; i++)
            #pragma unroll
            for (int j = 0; j < 6; j++) acc[i][j] += xr[i] * wc[j];
    }

    #pragma unroll
    for (int j = 0; j < 6; j++) {
        const int o = tx * 6 + j;
        const float bias = proj_b[o];
        #pragma unroll
        for (int i = 0; i < 8; i++) {
            const int m = m0 + ty * 8 + i;
            out[(size_t)m * 96 + o] = acc[i][j] + bias;
        }
    }
}

// ===========================================================================
extern "C" void kernel_launch(void* const* d_in, const int* in_sizes, int n_in,
                              void* d_out, int out_size)
{
    const float* x      = (const float*)d_in[0];
    const float* mask   = (const float*)d_in[1];
    const float* qkv_w  = (const float*)d_in[2];
    const float* qkv_b  = (const float*)d_in[3];
    const float* proj_w = (const float*)d_in[4];
    const float* proj_b = (const float*)d_in[5];
    float* out = (float*)d_out;

    const int smem1 = (128 * 100 + 96 * 98) * 4;   // 88832
    const int smem2 = (SEQ * 25 + SEQ * 26 + 96 * 25 + 96 * SSTR + 4 * 96 * 24) * 4; // 216576

    cudaFuncSetAttribute(qkv_kernel,  cudaFuncAttributeMaxDynamicSharedMemorySize, smem1);
    cudaFuncSetAttribute(attn_kernel, cudaFuncAttributeMaxDynamicSharedMemorySize, smem2);
    cudaFuncSetAttribute(proj_kernel, cudaFuncAttributeMaxDynamicSharedMemorySize, smem1);

    qkv_kernel<<<M_ROWS / 128, 256, smem1>>>(x, qkv_w, qkv_b);
    attn_kernel<<<B_WIN * NH, 256, smem2>>>(mask);
    proj_kernel<<<M_ROWS / 128, 256, smem1>>>(proj_w, proj_b, out);
}

// round 8
// speedup vs baseline: 1.5186x; 1.2304x over previous
#include <cuda_runtime.h>
#include <math.h>

#define B_WIN 1024
#define SEQ   288
#define CH    96
#define NH    4
#define HD    24
#define NW    128
#define M_ROWS (B_WIN * SEQ)   // 294912
#define SSTR  296              // S row stride: conflict-free mma stores

typedef unsigned long long u64;

// ---------------- f32x2 helpers (fast 64-bit LDS path) ---------------------
__device__ __forceinline__ void fma2(u64& d, u64 a, u64 b) {
    asm("fma.rn.f32x2 %0, %1, %2, %0;" : "+l"(d) : "l"(a), "l"(b));
}
__device__ __forceinline__ u64 dup2(float v) {
    u64 r; asm("mov.b64 %0, {%1, %2};" : "=l"(r) : "f"(v), "f"(v)); return r;
}
__device__ __forceinline__ u64 ld2s(const float* p) {
    float2 v = *(const float2*)p;
    u64 r; asm("mov.b64 %0, {%1, %2};" : "=l"(r) : "f"(v.x), "f"(v.y)); return r;
}
__device__ __forceinline__ float2 unp2(u64 v) {
    float2 f; asm("mov.b64 {%0, %1}, %2;" : "=f"(f.x), "=f"(f.y) : "l"(v)); return f;
}

// ---------------- tf32 mma helpers ----------------------------------------
__device__ __forceinline__ unsigned tf32_of(float f) {
    unsigned r; asm("cvt.rna.tf32.f32 %0, %1;" : "=r"(r) : "f"(f)); return r;
}
__device__ __forceinline__ float tf32f(float f) {
    return __uint_as_float(tf32_of(f));
}
__device__ __forceinline__ void mma_tf32(float* d, const unsigned* a, const unsigned* b) {
    asm volatile("mma.sync.aligned.m16n8k8.row.col.f32.tf32.tf32.f32 "
        "{%0,%1,%2,%3}, {%4,%5,%6,%7}, {%8,%9}, {%0,%1,%2,%3};"
        : "+f"(d[0]), "+f"(d[1]), "+f"(d[2]), "+f"(d[3])
        : "r"(a[0]), "r"(a[1]), "r"(a[2]), "r"(a[3]), "r"(b[0]), "r"(b[1]));
}

// ---------------- scratch (device globals; no runtime allocation) ----------
__device__ float g_Q[B_WIN * NH * SEQ * HD];   // q pre-scaled, tf32-rounded
__device__ float g_K[B_WIN * NH * SEQ * HD];
__device__ float g_V[B_WIN * NH * SEQ * HD];
__device__ float g_O[M_ROWS * CH];

// ===========================================================================
// Kernel 1: QKV projection (f32x2 form).  grid = M/128, block = 256, 2/SM.
// ===========================================================================
__global__ __launch_bounds__(256, 2) void qkv_kernel(
    const float* __restrict__ x,
    const float* __restrict__ qkv_w,
    const float* __restrict__ qkv_b)
{
    extern __shared__ float sm[];
    float* xs = sm;               // [128][100]
    float* ws = sm + 128 * 100;   // [96][98]  ws[k*98 + o] = w[cc+o][k]

    const int tid = threadIdx.x;
    const int m0  = blockIdx.x * 128;

    for (int idx = tid; idx < 128 * 24; idx += 256) {
        int r = idx / 24, c4 = idx % 24;
        float4 v = *(const float4*)(x + (size_t)(m0 + r) * 96 + c4 * 4);
        *(float4*)(xs + r * 100 + c4 * 4) = v;
    }

    const int tx = tid & 15;      // 16 col-groups of 6 (3 pairs)
    const int ty = tid >> 4;      // 16 row-groups of 8
    const float scale = 0.20412414523193154f; // 24^-0.5

    for (int s = 0; s < 3; ++s) {
        const int cc = s * 96;
        __syncthreads();
        for (int idx = tid; idx < 96 * 96; idx += 256) {
            int o = idx / 96, k = idx % 96;
            ws[k * 98 + o] = qkv_w[(size_t)(cc + o) * 96 + k];
        }
        __syncthreads();

        u64 acc[8][3];
        #pragma unroll
        for (int i = 0; i < 8; i++)
            #pragma unroll
            for (int j = 0; j < 3; j++) acc[i][j] = 0ULL;

        #pragma unroll 4
        for (int kk = 0; kk < 96; ++kk) {
            u64 xd[8], wp[3];
            #pragma unroll
            for (int i = 0; i < 8; i++) xd[i] = dup2(xs[(ty * 8 + i) * 100 + kk]);
            #pragma unroll
            for (int j = 0; j < 3; j++) wp[j] = ld2s(&ws[kk * 98 + tx * 6 + 2 * j]);
            #pragma unroll
            for (int i = 0; i < 8; i++)
                #pragma unroll
                for (int j = 0; j < 3; j++) fma2(acc[i][j], wp[j], xd[i]);
        }

        float* dst = (s == 0) ? g_Q : (s == 1) ? g_K : g_V;
        #pragma unroll
        for (int j = 0; j < 3; j++) {
            const int o  = tx * 6 + 2 * j;
            const int h  = o / 24;
            const int dd = o % 24;
            const float b0 = qkv_b[cc + o], b1 = qkv_b[cc + o + 1];
            #pragma unroll
            for (int i = 0; i < 8; i++) {
                const int m = m0 + ty * 8 + i;
                const int b = m / SEQ, n = m % SEQ;
                float2 v = unp2(acc[i][j]);
                v.x += b0; v.y += b1;
                if (s == 0) { v.x *= scale; v.y *= scale; }
                // pre-round to tf32 so attn smem fills are plain copies
                v.x = tf32f(v.x); v.y = tf32f(v.y);
                *(float2*)(dst + (((size_t)b * NH + h) * SEQ + n) * HD + dd) = v;
            }
        }
    }
}

// ===========================================================================
// Kernel 2: fused attention.  grid = 4096 (b,h), block = 512 (16 warps).
// All mma operands pre-rounded tf32 in smem -> inner loops are LDS+HMMA only.
// smem: Ks[288][25] + Vs[288][26] + Qs[96][25] + S[96][296] + Pred[4][96][24]
//     = 218880 B, 1 block/SM.
// QK: 216 m16n8 units, nt-major contiguous ranges (14/13 per warp), kb cached.
// softmax: 6 rows/warp, 2-row interleaved for MLP.
// PV: 24 (mt,kq) units over 16 warps; vb hoisted per ks across 3 nt.
// ===========================================================================
__global__ __launch_bounds__(512) void attn_kernel(const float* __restrict__ mask)
{
    extern __shared__ float sm[];
    float* Ks   = sm;                        // [288][25]
    float* Vs   = Ks + SEQ * 25;             // [288][26]
    float* Qs   = Vs + SEQ * 26;             // [96][25]
    float* S    = Qs + 96 * 25;              // [96][296]
    float* Pred = S  + 96 * SSTR;            // [4][96][24]

    const int tid = threadIdx.x;
    const int bh  = blockIdx.x;
    const int b   = bh >> 2;
    const int h   = bh & 3;
    const int w   = b & (NW - 1);
    const size_t base = (size_t)bh * SEQ * HD;

    for (int idx = tid; idx < SEQ * HD; idx += 512) {
        const int r = idx / HD, c = idx % HD;
        Ks[r * 25 + c] = g_K[base + idx];    // already tf32-rounded by qkv
        Vs[r * 26 + c] = g_V[base + idx];
    }

    const int wq   = tid >> 5;        // 0..15
    const int lane = tid & 31;
    const int gid  = lane >> 2;       // mma groupID (0..7)
    const int t4   = lane & 3;        // mma thread-in-group (0..3)

    // QK unit range (216 units, nt-major: uu = nt*6 + mt)
    const int u0   = wq * 13 + (wq < 8 ? wq : 8);
    const int ucnt = 13 + (wq < 8 ? 1 : 0);

    for (int qc = 0; qc < 3; ++qc) {
        const int n0 = qc * 96;
        __syncthreads();
        for (int idx = tid; idx < 96 * HD; idx += 512) {
            const int r = idx / HD, c = idx % HD;
            Qs[r * 25 + c] = g_Q[base + (size_t)n0 * HD + idx];
        }
        __syncthreads();

        // ---- S = Q K^T -------------------------------------------------
        {
            int cur_nt = -1;
            unsigned kb[3][2];
            for (int u = u0; u < u0 + ucnt; ++u) {
                const int nt = u / 6;
                const int mt = u - nt * 6;
                if (nt != cur_nt) {
                    cur_nt = nt;
                    const float* kr = Ks + (nt * 8 + gid) * 25 + t4;
                    #pragma unroll
                    for (int ks = 0; ks < 3; ks++) {
                        kb[ks][0] = __float_as_uint(kr[ks * 8]);
                        kb[ks][1] = __float_as_uint(kr[ks * 8 + 4]);
                    }
                }
                const float* q0 = Qs + (mt * 16 + gid) * 25 + t4;
                const float* q1 = q0 + 8 * 25;
                float acc[4] = {0.f, 0.f, 0.f, 0.f};
                #pragma unroll
                for (int ks = 0; ks < 3; ks++) {
                    unsigned qa[4];
                    qa[0] = __float_as_uint(q0[ks * 8]);
                    qa[1] = __float_as_uint(q1[ks * 8]);
                    qa[2] = __float_as_uint(q0[ks * 8 + 4]);
                    qa[3] = __float_as_uint(q1[ks * 8 + 4]);
                    mma_tf32(acc, qa, kb[ks]);
                }
                float* s0 = S + (mt * 16 + gid) * SSTR + nt * 8 + t4 * 2;
                *(float2*)s0              = make_float2(acc[0], acc[1]);
                *(float2*)(s0 + 8 * SSTR) = make_float2(acc[2], acc[3]);
            }
        }
        __syncthreads();

        // ---- mask + softmax: 6 rows/warp, 2-row interleaved ------------
        for (int t = 0; t < 6; t += 2) {
            const int ra = wq * 6 + t, rb = ra + 1;
            const float* ma = mask + ((size_t)w * SEQ + (n0 + ra)) * SEQ;
            const float* mb = mask + ((size_t)w * SEQ + (n0 + rb)) * SEQ;
            float va[9], vb[9];
            float mxa = -1e30f, mxb = -1e30f;
            #pragma unroll
            for (int q = 0; q < 9; q++) {
                const int c = lane + 32 * q;
                va[q] = S[ra * SSTR + c] + __ldg(ma + c);
                vb[q] = S[rb * SSTR + c] + __ldg(mb + c);
                mxa = fmaxf(mxa, va[q]);
                mxb = fmaxf(mxb, vb[q]);
            }
            #pragma unroll
            for (int off = 16; off; off >>= 1) {
                mxa = fmaxf(mxa, __shfl_xor_sync(0xffffffffu, mxa, off));
                mxb = fmaxf(mxb, __shfl_xor_sync(0xffffffffu, mxb, off));
            }
            float sa = 0.f, sb = 0.f;
            #pragma unroll
            for (int q = 0; q < 9; q++) {
                va[q] = __expf(va[q] - mxa); sa += va[q];
                vb[q] = __expf(vb[q] - mxb); sb += vb[q];
            }
            #pragma unroll
            for (int off = 16; off; off >>= 1) {
                sa += __shfl_xor_sync(0xffffffffu, sa, off);
                sb += __shfl_xor_sync(0xffffffffu, sb, off);
            }
            const float ia = 1.f / sa, ib = 1.f / sb;
            #pragma unroll
            for (int q = 0; q < 9; q++) {
                const int c = lane + 32 * q;
                S[ra * SSTR + c] = tf32f(va[q] * ia);   // pre-round for PV mma
                S[rb * SSTR + c] = tf32f(vb[q] * ib);
            }
        }
        __syncthreads();

        // ---- O = P V  (24 units over 16 warps; vb hoisted per ks) ------
        for (int uu = wq; uu < 24; uu += 16) {
            const int mt = uu >> 2, kq = uu & 3;
            float acc[3][4];
            #pragma unroll
            for (int nt = 0; nt < 3; nt++)
                #pragma unroll
                for (int r = 0; r < 4; r++) acc[nt][r] = 0.f;

            #pragma unroll 3
            for (int ks = 0; ks < 9; ks++) {
                const int k0 = kq * 72 + ks * 8;
                unsigned vbf[3][2];
                #pragma unroll
                for (int nt = 0; nt < 3; nt++) {
                    vbf[nt][0] = __float_as_uint(Vs[(k0 + t4) * 26 + nt * 8 + gid]);
                    vbf[nt][1] = __float_as_uint(Vs[(k0 + 4 + t4) * 26 + nt * 8 + gid]);
                }
                const float* p0 = S + (mt * 16 + gid) * SSTR + k0 + t4;
                const float* p1 = p0 + 8 * SSTR;
                unsigned pa[4];
                pa[0] = __float_as_uint(p0[0]);
                pa[1] = __float_as_uint(p1[0]);
                pa[2] = __float_as_uint(p0[4]);
                pa[3] = __float_as_uint(p1[4]);
                #pragma unroll
                for (int nt = 0; nt < 3; nt++) mma_tf32(acc[nt], pa, vbf[nt]);
            }
            float* pr = Pred + kq * (96 * 24);
            #pragma unroll
            for (int nt = 0; nt < 3; nt++) {
                const int c = nt * 8 + t4 * 2;
                *(float2*)(pr + (mt * 16 + gid) * 24 + c) =
                    make_float2(acc[nt][0], acc[nt][1]);
                *(float2*)(pr + (mt * 16 + 8 + gid) * 24 + c) =
                    make_float2(acc[nt][2], acc[nt][3]);
            }
        }
        __syncthreads();

        // ---- reduce 4 k-quarters, write O ------------------------------
        for (int e = tid; e < 96 * 24; e += 512) {
            const float s = Pred[e] + Pred[e + 2304] + Pred[e + 4608] + Pred[e + 6912];
            const int r = e / 24, c = e % 24;
            g_O[((size_t)b * SEQ + n0 + r) * CH + h * HD + c] = s;
        }
    }
}

// ===========================================================================
// Kernel 3: output projection (f32x2 form).  grid = M/128, block = 256, 2/SM.
// ===========================================================================
__global__ __launch_bounds__(256, 2) void proj_kernel(
    const float* __restrict__ proj_w,
    const float* __restrict__ proj_b,
    float* __restrict__ out)
{
    extern __shared__ float sm[];
    float* xs = sm;               // [128][100]
    float* ws = sm + 128 * 100;   // [96][98]

    const int tid = threadIdx.x;
    const int m0  = blockIdx.x * 128;

    for (int idx = tid; idx < 128 * 24; idx += 256) {
        int r = idx / 24, c4 = idx % 24;
        float4 v = *(const float4*)(g_O + (size_t)(m0 + r) * 96 + c4 * 4);
        *(float4*)(xs + r * 100 + c4 * 4) = v;
    }
    for (int idx = tid; idx < 96 * 96; idx += 256) {
        int o = idx / 96, k = idx % 96;
        ws[k * 98 + o] = proj_w[(size_t)o * 96 + k];
    }
    __syncthreads();

    const int tx = tid & 15, ty = tid >> 4;
    u64 acc[8][3];
    #pragma unroll
    for (int i = 0; i < 8; i++)
        #pragma unroll
        for (int j = 0; j < 3; j++) acc[i][j] = 0ULL;

    #pragma unroll 4
    for (int kk = 0; kk < 96; ++kk) {
        u64 xd[8], wp[3];
        #pragma unroll
        for (int i = 0; i < 8; i++) xd[i] = dup2(xs[(ty * 8 + i) * 100 + kk]);
        #pragma unroll
        for (int j = 0; j < 3; j++) wp[j] = ld2s(&ws[kk * 98 + tx * 6 + 2 * j]);
        #pragma unroll
        for (int i = 0; i < 8; i++)
            #pragma unroll
            for (int j = 0; j < 3; j++) fma2(acc[i][j], wp[j], xd[i]);
    }

    #pragma unroll
    for (int j = 0; j < 3; j++) {
        const int o = tx * 6 + 2 * j;
        const float b0 = proj_b[o], b1 = proj_b[o + 1];
        #pragma unroll
        for (int i = 0; i < 8; i++) {
            const int m = m0 + ty * 8 + i;
            float2 v = unp2(acc[i][j]);
            *(float2*)(out + (size_t)m * 96 + o) = make_float2(v.x + b0, v.y + b1);
        }
    }
}

// ===========================================================================
extern "C" void kernel_launch(void* const* d_in, const int* in_sizes, int n_in,
                              void* d_out, int out_size)
{
    const float* x      = (const float*)d_in[0];
    const float* mask   = (const float*)d_in[1];
    const float* qkv_w  = (const float*)d_in[2];
    const float* qkv_b  = (const float*)d_in[3];
    const float* proj_w = (const float*)d_in[4];
    const float* proj_b = (const float*)d_in[5];
    float* out = (float*)d_out;

    const int smem1 = (128 * 100 + 96 * 98) * 4;   // 88832
    const int smem2 = (SEQ * 25 + SEQ * 26 + 96 * 25 + 96 * SSTR + 4 * 96 * 24) * 4; // 218880

    cudaFuncSetAttribute(qkv_kernel,  cudaFuncAttributeMaxDynamicSharedMemorySize, smem1);
    cudaFuncSetAttribute(attn_kernel, cudaFuncAttributeMaxDynamicSharedMemorySize, smem2);
    cudaFuncSetAttribute(proj_kernel, cudaFuncAttributeMaxDynamicSharedMemorySize, smem1);

    qkv_kernel<<<M_ROWS / 128, 256, smem1>>>(x, qkv_w, qkv_b);
    attn_kernel<<<B_WIN * NH, 512, smem2>>>(mask);
    proj_kernel<<<M_ROWS / 128, 256, smem1>>>(proj_w, proj_b, out);
}

// round 10
// speedup vs baseline: 1.7885x; 1.1777x over previous
#include <cuda_runtime.h>
#include <math.h>

#define B_WIN 1024
#define SEQ   288
#define CH    96
#define NH    4
#define HD    24
#define NW    128
#define M_ROWS (B_WIN * SEQ)   // 294912
#define SSTR  296              // S row stride: conflict-free mma stores

typedef unsigned long long u64;

// ---------------- f32x2 helpers (fast 64-bit LDS path) ---------------------
__device__ __forceinline__ void fma2(u64& d, u64 a, u64 b) {
    asm("fma.rn.f32x2 %0, %1, %2, %0;" : "+l"(d) : "l"(a), "l"(b));
}
__device__ __forceinline__ u64 dup2(float v) {
    u64 r; asm("mov.b64 %0, {%1, %2};" : "=l"(r) : "f"(v), "f"(v)); return r;
}
__device__ __forceinline__ u64 ld2s(const float* p) {
    float2 v = *(const float2*)p;
    u64 r; asm("mov.b64 %0, {%1, %2};" : "=l"(r) : "f"(v.x), "f"(v.y)); return r;
}
__device__ __forceinline__ float2 unp2(u64 v) {
    float2 f; asm("mov.b64 {%0, %1}, %2;" : "=f"(f.x), "=f"(f.y) : "l"(v)); return f;
}

// ---------------- tf32 mma helpers ----------------------------------------
__device__ __forceinline__ unsigned tf32_of(float f) {
    unsigned r; asm("cvt.rna.tf32.f32 %0, %1;" : "=r"(r) : "f"(f)); return r;
}
__device__ __forceinline__ float tf32f(float f) {
    return __uint_as_float(tf32_of(f));
}
__device__ __forceinline__ void mma_tf32(float* d, const unsigned* a, const unsigned* b) {
    asm volatile("mma.sync.aligned.m16n8k8.row.col.f32.tf32.tf32.f32 "
        "{%0,%1,%2,%3}, {%4,%5,%6,%7}, {%8,%9}, {%0,%1,%2,%3};"
        : "+f"(d[0]), "+f"(d[1]), "+f"(d[2]), "+f"(d[3])
        : "r"(a[0]), "r"(a[1]), "r"(a[2]), "r"(a[3]), "r"(b[0]), "r"(b[1]));
}

// ---------------- scratch (device globals; no runtime allocation) ----------
__device__ float g_Q[B_WIN * NH * SEQ * HD];   // q pre-scaled, tf32-rounded
__device__ float g_K[B_WIN * NH * SEQ * HD];
__device__ float g_V[B_WIN * NH * SEQ * HD];
__device__ float g_O[M_ROWS * CH];

// ===========================================================================
// Kernel 1: QKV projection on tensor cores (tf32 mma).
// grid = M/128, block = 512 (16 warps).  warp = (m16-tile, nt-half).
// smem: xs[128][100] + wsm[288][100], both tf32-rounded  (166400 B)
// D[m][col] = sum_k x[m][k] * W[col][k];  col 0-95 -> Q(*scale), 96-191 -> K,
// 192-287 -> V, scattered to [b][h][n][d] layout with tf32 rounding.
// ===========================================================================
__global__ __launch_bounds__(512) void qkv_kernel(
    const float* __restrict__ x,
    const float* __restrict__ qkv_w,
    const float* __restrict__ qkv_b)
{
    extern __shared__ float sm[];
    float* xs  = sm;               // [128][100]
    float* wsm = sm + 128 * 100;   // [288][100]

    const int tid = threadIdx.x;
    const int m0  = blockIdx.x * 128;

    // x tile: tf32-rounded
    for (int idx = tid; idx < 128 * 24; idx += 512) {
        int r = idx / 24, c4 = idx % 24;
        float4 v = *(const float4*)(x + (size_t)(m0 + r) * 96 + c4 * 4);
        v.x = tf32f(v.x); v.y = tf32f(v.y); v.z = tf32f(v.z); v.w = tf32f(v.w);
        *(float4*)(xs + r * 100 + c4 * 4) = v;
    }
    // full W: tf32-rounded
    for (int idx = tid; idx < 288 * 96; idx += 512) {
        int n = idx / 96, k = idx % 96;
        wsm[n * 100 + k] = tf32f(qkv_w[(size_t)n * 96 + k]);
    }
    __syncthreads();

    const int wq   = tid >> 5;       // 0..15
    const int lane = tid & 31;
    const int gid  = lane >> 2;
    const int t4   = lane & 3;
    const int mt   = wq & 7;         // m16-tile
    const int nt0  = (wq >> 3) * 18; // nt half: 0-17 or 18-35
    const float scale = 0.20412414523193154f;

    // cache A (x) fragments for this m-tile: 12 k-steps
    unsigned xa[12][4];
    {
        const float* x0 = xs + (mt * 16 + gid) * 100 + t4;
        const float* x1 = x0 + 8 * 100;
        #pragma unroll
        for (int ks = 0; ks < 12; ks++) {
            xa[ks][0] = __float_as_uint(x0[ks * 8]);
            xa[ks][1] = __float_as_uint(x1[ks * 8]);
            xa[ks][2] = __float_as_uint(x0[ks * 8 + 4]);
            xa[ks][3] = __float_as_uint(x1[ks * 8 + 4]);
        }
    }

    const int ma = m0 + mt * 16 + gid;       // row for acc[0],acc[1]
    const int mb = ma + 8;                    // row for acc[2],acc[3]
    const int ba = ma / SEQ, na = ma % SEQ;
    const int bb = mb / SEQ, nb = mb % SEQ;

    for (int nt = nt0; nt < nt0 + 18; ++nt) {
        float acc[4] = {0.f, 0.f, 0.f, 0.f};
        const float* wr = wsm + (nt * 8 + gid) * 100 + t4;
        #pragma unroll
        for (int ks = 0; ks < 12; ks++) {
            unsigned wb[2];
            wb[0] = __float_as_uint(wr[ks * 8]);
            wb[1] = __float_as_uint(wr[ks * 8 + 4]);
            mma_tf32(acc, xa[ks], wb);
        }
        // epilogue: col = nt*8 + 2*t4 (+1); head-fixed within nt
        const int col = nt * 8 + t4 * 2;
        const int s   = col / 96;            // 0=Q 1=K 2=V
        const int within = col - s * 96;
        const int h   = within / 24;
        const int dd  = within - h * 24;     // even
        float* dst = (s == 0) ? g_Q : (s == 1) ? g_K : g_V;
        const float b0 = qkv_b[col], b1 = qkv_b[col + 1];
        float2 va = make_float2(acc[0] + b0, acc[1] + b1);
        float2 vb = make_float2(acc[2] + b0, acc[3] + b1);
        if (s == 0) { va.x *= scale; va.y *= scale; vb.x *= scale; vb.y *= scale; }
        va.x = tf32f(va.x); va.y = tf32f(va.y);
        vb.x = tf32f(vb.x); vb.y = tf32f(vb.y);
        *(float2*)(dst + (((size_t)ba * NH + h) * SEQ + na) * HD + dd) = va;
        *(float2*)(dst + (((size_t)bb * NH + h) * SEQ + nb) * HD + dd) = vb;
    }
}

// ===========================================================================
// Kernel 2: fused attention.  grid = 4096 (b,h), block = 512 (16 warps).
// All mma operands pre-rounded tf32 in smem -> inner loops are LDS+HMMA only.
// smem: Ks[288][25] + Vs[288][26] + Qs[96][25] + S[96][296] + Pred[4][96][24]
//     = 218880 B, 1 block/SM.
// softmax: no max subtraction (logits bounded |s+m| < ~6.5).
// ===========================================================================
__global__ __launch_bounds__(512) void attn_kernel(const float* __restrict__ mask)
{
    extern __shared__ float sm[];
    float* Ks   = sm;                        // [288][25]
    float* Vs   = Ks + SEQ * 25;             // [288][26]
    float* Qs   = Vs + SEQ * 26;             // [96][25]
    float* S    = Qs + 96 * 25;              // [96][296]
    float* Pred = S  + 96 * SSTR;            // [4][96][24]

    const int tid = threadIdx.x;
    const int bh  = blockIdx.x;
    const int b   = bh >> 2;
    const int h   = bh & 3;
    const int w   = b & (NW - 1);
    const size_t base = (size_t)bh * SEQ * HD;

    for (int idx = tid; idx < SEQ * HD; idx += 512) {
        const int r = idx / HD, c = idx % HD;
        Ks[r * 25 + c] = g_K[base + idx];    // already tf32-rounded by qkv
        Vs[r * 26 + c] = g_V[base + idx];
    }

    const int wq   = tid >> 5;        // 0..15
    const int lane = tid & 31;
    const int gid  = lane >> 2;
    const int t4   = lane & 3;

    // QK unit range (216 units, nt-major: uu = nt*6 + mt)
    const int u0   = wq * 13 + (wq < 8 ? wq : 8);
    const int ucnt = 13 + (wq < 8 ? 1 : 0);

    for (int qc = 0; qc < 3; ++qc) {
        const int n0 = qc * 96;
        __syncthreads();
        for (int idx = tid; idx < 96 * HD; idx += 512) {
            const int r = idx / HD, c = idx % HD;
            Qs[r * 25 + c] = g_Q[base + (size_t)n0 * HD + idx];
        }
        __syncthreads();

        // ---- S = Q K^T -------------------------------------------------
        {
            int cur_nt = -1;
            unsigned kb[3][2];
            for (int u = u0; u < u0 + ucnt; ++u) {
                const int nt = u / 6;
                const int mt = u - nt * 6;
                if (nt != cur_nt) {
                    cur_nt = nt;
                    const float* kr = Ks + (nt * 8 + gid) * 25 + t4;
                    #pragma unroll
                    for (int ks = 0; ks < 3; ks++) {
                        kb[ks][0] = __float_as_uint(kr[ks * 8]);
                        kb[ks][1] = __float_as_uint(kr[ks * 8 + 4]);
                    }
                }
                const float* q0 = Qs + (mt * 16 + gid) * 25 + t4;
                const float* q1 = q0 + 8 * 25;
                float acc[4] = {0.f, 0.f, 0.f, 0.f};
                #pragma unroll
                for (int ks = 0; ks < 3; ks++) {
                    unsigned qa[4];
                    qa[0] = __float_as_uint(q0[ks * 8]);
                    qa[1] = __float_as_uint(q1[ks * 8]);
                    qa[2] = __float_as_uint(q0[ks * 8 + 4]);
                    qa[3] = __float_as_uint(q1[ks * 8 + 4]);
                    mma_tf32(acc, qa, kb[ks]);
                }
                float* s0 = S + (mt * 16 + gid) * SSTR + nt * 8 + t4 * 2;
                *(float2*)s0              = make_float2(acc[0], acc[1]);
                *(float2*)(s0 + 8 * SSTR) = make_float2(acc[2], acc[3]);
            }
        }
        __syncthreads();

        // ---- mask + softmax (no max-sub): 6 rows/warp, 2-row interleave
        for (int t = 0; t < 6; t += 2) {
            const int ra = wq * 6 + t, rb = ra + 1;
            const float* ma = mask + ((size_t)w * SEQ + (n0 + ra)) * SEQ;
            const float* mb = mask + ((size_t)w * SEQ + (n0 + rb)) * SEQ;
            float va[9], vb[9];
            #pragma unroll
            for (int q = 0; q < 9; q++) {
                const int c = lane + 32 * q;
                va[q] = __expf(S[ra * SSTR + c] + __ldg(ma + c));
                vb[q] = __expf(S[rb * SSTR + c] + __ldg(mb + c));
            }
            float sa = 0.f, sb = 0.f;
            #pragma unroll
            for (int q = 0; q < 9; q++) { sa += va[q]; sb += vb[q]; }
            #pragma unroll
            for (int off = 16; off; off >>= 1) {
                sa += __shfl_xor_sync(0xffffffffu, sa, off);
                sb += __shfl_xor_sync(0xffffffffu, sb, off);
            }
            const float ia = 1.f / sa, ib = 1.f / sb;
            #pragma unroll
            for (int q = 0; q < 9; q++) {
                const int c = lane + 32 * q;
                S[ra * SSTR + c] = tf32f(va[q] * ia);   // pre-round for PV mma
                S[rb * SSTR + c] = tf32f(vb[q] * ib);
            }
        }
        __syncthreads();

        // ---- O = P V  (24 units over 16 warps; vb hoisted per ks) ------
        for (int uu = wq; uu < 24; uu += 16) {
            const int mt = uu >> 2, kq = uu & 3;
            float acc[3][4];
            #pragma unroll
            for (int nt = 0; nt < 3; nt++)
                #pragma unroll
                for (int r = 0; r < 4; r++) acc[nt][r] = 0.f;

            #pragma unroll 3
            for (int ks = 0; ks < 9; ks++) {
                const int k0 = kq * 72 + ks * 8;
                unsigned vbf[3][2];
                #pragma unroll
                for (int nt = 0; nt < 3; nt++) {
                    vbf[nt][0] = __float_as_uint(Vs[(k0 + t4) * 26 + nt * 8 + gid]);
                    vbf[nt][1] = __float_as_uint(Vs[(k0 + 4 + t4) * 26 + nt * 8 + gid]);
                }
                const float* p0 = S + (mt * 16 + gid) * SSTR + k0 + t4;
                const float* p1 = p0 + 8 * SSTR;
                unsigned pa[4];
                pa[0] = __float_as_uint(p0[0]);
                pa[1] = __float_as_uint(p1[0]);
                pa[2] = __float_as_uint(p0[4]);
                pa[3] = __float_as_uint(p1[4]);
                #pragma unroll
                for (int nt = 0; nt < 3; nt++) mma_tf32(acc[nt], pa, vbf[nt]);
            }
            float* pr = Pred + kq * (96 * 24);
            #pragma unroll
            for (int nt = 0; nt < 3; nt++) {
                const int c = nt * 8 + t4 * 2;
                *(float2*)(pr + (mt * 16 + gid) * 24 + c) =
                    make_float2(acc[nt][0], acc[nt][1]);
                *(float2*)(pr + (mt * 16 + 8 + gid) * 24 + c) =
                    make_float2(acc[nt][2], acc[nt][3]);
            }
        }
        __syncthreads();

        // ---- reduce 4 k-quarters, write O ------------------------------
        for (int e = tid; e < 96 * 24; e += 512) {
            const float s = Pred[e] + Pred[e + 2304] + Pred[e + 4608] + Pred[e + 6912];
            const int r = e / 24, c = e % 24;
            g_O[((size_t)b * SEQ + n0 + r) * CH + h * HD + c] = s;
        }
    }
}

// ===========================================================================
// Kernel 3: output projection (f32x2 form).  grid = M/128, block = 256, 2/SM.
// ===========================================================================
__global__ __launch_bounds__(256, 2) void proj_kernel(
    const float* __restrict__ proj_w,
    const float* __restrict__ proj_b,
    float* __restrict__ out)
{
    extern __shared__ float sm[];
    float* xs = sm;               // [128][100]
    float* ws = sm + 128 * 100;   // [96][98]

    const int tid = threadIdx.x;
    const int m0  = blockIdx.x * 128;

    for (int idx = tid; idx < 128 * 24; idx += 256) {
        int r = idx / 24, c4 = idx % 24;
        float4 v = *(const float4*)(g_O + (size_t)(m0 + r) * 96 + c4 * 4);
        *(float4*)(xs + r * 100 + c4 * 4) = v;
    }
    for (int idx = tid; idx < 96 * 96; idx += 256) {
        int o = idx / 96, k = idx % 96;
        ws[k * 98 + o] = proj_w[(size_t)o * 96 + k];
    }
    __syncthreads();

    const int tx = tid & 15, ty = tid >> 4;
    u64 acc[8][3];
    #pragma unroll
    for (int i = 0; i < 8; i++)
        #pragma unroll
        for (int j = 0; j < 3; j++) acc[i][j] = 0ULL;

    #pragma unroll 4
    for (int kk = 0; kk < 96; ++kk) {
        u64 xd[8], wp[3];
        #pragma unroll
        for (int i = 0; i < 8; i++) xd[i] = dup2(xs[(ty * 8 + i) * 100 + kk]);
        #pragma unroll
        for (int j = 0; j < 3; j++) wp[j] = ld2s(&ws[kk * 98 + tx * 6 + 2 * j]);
        #pragma unroll
        for (int i = 0; i < 8; i++)
            #pragma unroll
            for (int j = 0; j < 3; j++) fma2(acc[i][j], wp[j], xd[i]);
    }

    #pragma unroll
    for (int j = 0; j < 3; j++) {
        const int o = tx * 6 + 2 * j;
        const float b0 = proj_b[o], b1 = proj_b[o + 1];
        #pragma unroll
        for (int i = 0; i < 8; i++) {
            const int m = m0 + ty * 8 + i;
            float2 v = unp2(acc[i][j]);
            *(float2*)(out + (size_t)m * 96 + o) = make_float2(v.x + b0, v.y + b1);
        }
    }
}

// ===========================================================================
extern "C" void kernel_launch(void* const* d_in, const int* in_sizes, int n_in,
                              void* d_out, int out_size)
{
    const float* x      = (const float*)d_in[0];
    const float* mask   = (const float*)d_in[1];
    const float* qkv_w  = (const float*)d_in[2];
    const float* qkv_b  = (const float*)d_in[3];
    const float* proj_w = (const float*)d_in[4];
    const float* proj_b = (const float*)d_in[5];
    float* out = (float*)d_out;

    const int smemQ = (128 * 100 + 288 * 100) * 4;  // 166400
    const int smemA = (SEQ * 25 + SEQ * 26 + 96 * 25 + 96 * SSTR + 4 * 96 * 24) * 4; // 218880
    const int smemP = (128 * 100 + 96 * 98) * 4;    // 88832

    cudaFuncSetAttribute(qkv_kernel,  cudaFuncAttributeMaxDynamicSharedMemorySize, smemQ);
    cudaFuncSetAttribute(attn_kernel, cudaFuncAttributeMaxDynamicSharedMemorySize, smemA);
    cudaFuncSetAttribute(proj_kernel, cudaFuncAttributeMaxDynamicSharedMemorySize, smemP);

    qkv_kernel<<<M_ROWS / 128, 512, smemQ>>>(x, qkv_w, qkv_b);
    attn_kernel<<<B_WIN * NH, 512, smemA>>>(mask);
    proj_kernel<<<M_ROWS / 128, 256, smemP>>>(proj_w, proj_b, out);
}

// round 11
// speedup vs baseline: 2.0445x; 1.1432x over previous
#include <cuda_runtime.h>
#include <math.h>

#define B_WIN 1024
#define SEQ   288
#define CH    96
#define NH    4
#define HD    24
#define NW    128
#define M_ROWS (B_WIN * SEQ)   // 294912
#define SSTR  296              // S row stride: conflict-free mma stores

// ---------------- tf32 mma helpers ----------------------------------------
__device__ __forceinline__ unsigned tf32_of(float f) {
    unsigned r; asm("cvt.rna.tf32.f32 %0, %1;" : "=r"(r) : "f"(f)); return r;
}
__device__ __forceinline__ float tf32f(float f) {
    return __uint_as_float(tf32_of(f));
}
__device__ __forceinline__ void mma_tf32(float* d, const unsigned* a, const unsigned* b) {
    asm volatile("mma.sync.aligned.m16n8k8.row.col.f32.tf32.tf32.f32 "
        "{%0,%1,%2,%3}, {%4,%5,%6,%7}, {%8,%9}, {%0,%1,%2,%3};"
        : "+f"(d[0]), "+f"(d[1]), "+f"(d[2]), "+f"(d[3])
        : "r"(a[0]), "r"(a[1]), "r"(a[2]), "r"(a[3]), "r"(b[0]), "r"(b[1]));
}

// ---------------- scratch (device globals; no runtime allocation) ----------
__device__ float g_Q[B_WIN * NH * SEQ * HD];   // q pre-scaled, tf32-rounded
__device__ float g_K[B_WIN * NH * SEQ * HD];
__device__ float g_V[B_WIN * NH * SEQ * HD];
__device__ float g_O[M_ROWS * CH];

// ===========================================================================
// Kernel 1: QKV projection on tensor cores (tf32 mma).  Unchanged from R10.
// grid = M/128, block = 512 (16 warps).  warp = (m16-tile, nt-half).
// ===========================================================================
__global__ __launch_bounds__(512) void qkv_kernel(
    const float* __restrict__ x,
    const float* __restrict__ qkv_w,
    const float* __restrict__ qkv_b)
{
    extern __shared__ float sm[];
    float* xs  = sm;               // [128][100]
    float* wsm = sm + 128 * 100;   // [288][100]

    const int tid = threadIdx.x;
    const int m0  = blockIdx.x * 128;

    for (int idx = tid; idx < 128 * 24; idx += 512) {
        int r = idx / 24, c4 = idx % 24;
        float4 v = *(const float4*)(x + (size_t)(m0 + r) * 96 + c4 * 4);
        v.x = tf32f(v.x); v.y = tf32f(v.y); v.z = tf32f(v.z); v.w = tf32f(v.w);
        *(float4*)(xs + r * 100 + c4 * 4) = v;
    }
    for (int idx = tid; idx < 288 * 96; idx += 512) {
        int n = idx / 96, k = idx % 96;
        wsm[n * 100 + k] = tf32f(qkv_w[(size_t)n * 96 + k]);
    }
    __syncthreads();

    const int wq   = tid >> 5;
    const int lane = tid & 31;
    const int gid  = lane >> 2;
    const int t4   = lane & 3;
    const int mt   = wq & 7;
    const int nt0  = (wq >> 3) * 18;
    const float scale = 0.20412414523193154f;

    unsigned xa[12][4];
    {
        const float* x0 = xs + (mt * 16 + gid) * 100 + t4;
        const float* x1 = x0 + 8 * 100;
        #pragma unroll
        for (int ks = 0; ks < 12; ks++) {
            xa[ks][0] = __float_as_uint(x0[ks * 8]);
            xa[ks][1] = __float_as_uint(x1[ks * 8]);
            xa[ks][2] = __float_as_uint(x0[ks * 8 + 4]);
            xa[ks][3] = __float_as_uint(x1[ks * 8 + 4]);
        }
    }

    const int ma = m0 + mt * 16 + gid;
    const int mb = ma + 8;
    const int ba = ma / SEQ, na = ma % SEQ;
    const int bb = mb / SEQ, nb = mb % SEQ;

    for (int nt = nt0; nt < nt0 + 18; ++nt) {
        float acc[4] = {0.f, 0.f, 0.f, 0.f};
        const float* wr = wsm + (nt * 8 + gid) * 100 + t4;
        #pragma unroll
        for (int ks = 0; ks < 12; ks++) {
            unsigned wb[2];
            wb[0] = __float_as_uint(wr[ks * 8]);
            wb[1] = __float_as_uint(wr[ks * 8 + 4]);
            mma_tf32(acc, xa[ks], wb);
        }
        const int col = nt * 8 + t4 * 2;
        const int s   = col / 96;
        const int within = col - s * 96;
        const int h   = within / 24;
        const int dd  = within - h * 24;
        float* dst = (s == 0) ? g_Q : (s == 1) ? g_K : g_V;
        const float b0 = qkv_b[col], b1 = qkv_b[col + 1];
        float2 va = make_float2(acc[0] + b0, acc[1] + b1);
        float2 vb = make_float2(acc[2] + b0, acc[3] + b1);
        if (s == 0) { va.x *= scale; va.y *= scale; vb.x *= scale; vb.y *= scale; }
        va.x = tf32f(va.x); va.y = tf32f(va.y);
        vb.x = tf32f(vb.x); vb.y = tf32f(vb.y);
        *(float2*)(dst + (((size_t)ba * NH + h) * SEQ + na) * HD + dd) = va;
        *(float2*)(dst + (((size_t)bb * NH + h) * SEQ + nb) * HD + dd) = vb;
    }
}

// ===========================================================================
// Kernel 2: fused attention.  grid = 4096 (b,h), block = 384 (12 warps).
// warp = (mt 0..5, half 0..1): 16 rows x 144 cols of S in registers.
// QK acc stays in regs; mask+exp applied in epilogue; S written ONCE.
// Q-frags loaded directly from gmem (L2-resident); K-frags from Ks smem.
// PV: 36 units (6mt x 3nt x 2kq) = 3/warp, balanced; 2-way Pred reduce.
// smem: Ks[288][25] + Vs[288][26] + S[96][296] + Pred[2][96][24] + rowsum[192]
//     = 191616 B.  3 syncthreads per chunk.
// ===========================================================================
__global__ __launch_bounds__(384) void attn_kernel(const float* __restrict__ mask)
{
    extern __shared__ float sm[];
    float* Ks     = sm;                      // [288][25]
    float* Vs     = Ks + SEQ * 25;           // [288][26]
    float* S      = Vs + SEQ * 26;           // [96][296]
    float* Pred   = S  + 96 * SSTR;          // [2][96][24]
    float* rowsum = Pred + 2 * 96 * 24;      // [2][96]

    const int tid = threadIdx.x;
    const int bh  = blockIdx.x;
    const int b   = bh >> 2;
    const int h   = bh & 3;
    const int w   = b & (NW - 1);
    const size_t base = (size_t)bh * SEQ * HD;

    for (int idx = tid; idx < SEQ * HD; idx += 384) {
        const int r = idx / HD, c = idx % HD;
        Ks[r * 25 + c] = g_K[base + idx];    // already tf32-rounded by qkv
        Vs[r * 26 + c] = g_V[base + idx];
    }
    __syncthreads();

    const int wq   = tid >> 5;        // 0..11
    const int lane = tid & 31;
    const int gid  = lane >> 2;
    const int t4   = lane & 3;
    const int mt   = wq >> 1;         // 0..5
    const int half = wq & 1;          // 0..1

    for (int qc = 0; qc < 3; ++qc) {
        const int n0 = qc * 96;

        // ---- QK: 18 n-tiles, acc in registers --------------------------
        unsigned qa[3][4];
        {
            const float* q0 = g_Q + base + (size_t)(n0 + mt * 16 + gid) * HD + t4;
            const float* q1 = q0 + 8 * HD;
            #pragma unroll
            for (int ks = 0; ks < 3; ks++) {
                qa[ks][0] = __float_as_uint(q0[ks * 8]);
                qa[ks][1] = __float_as_uint(q1[ks * 8]);
                qa[ks][2] = __float_as_uint(q0[ks * 8 + 4]);
                qa[ks][3] = __float_as_uint(q1[ks * 8 + 4]);
            }
        }
        float acc[18][4];
        #pragma unroll
        for (int ntl = 0; ntl < 18; ntl++) {
            acc[ntl][0] = acc[ntl][1] = acc[ntl][2] = acc[ntl][3] = 0.f;
            const int nt = half * 18 + ntl;
            const float* kr = Ks + (nt * 8 + gid) * 25 + t4;
            #pragma unroll
            for (int ks = 0; ks < 3; ks++) {
                unsigned kb[2];
                kb[0] = __float_as_uint(kr[ks * 8]);
                kb[1] = __float_as_uint(kr[ks * 8 + 4]);
                mma_tf32(acc[ntl], qa[ks], kb);
            }
        }

        // ---- mask + exp on register accumulators ----------------------
        const int rowa = n0 + mt * 16 + gid;
        const float* ma = mask + ((size_t)w * SEQ + rowa) * SEQ;
        const float* mb = ma + 8 * SEQ;
        float sa = 0.f, sb = 0.f;
        #pragma unroll
        for (int ntl = 0; ntl < 18; ntl++) {
            const int col = (half * 18 + ntl) * 8 + t4 * 2;
            float2 mva = *(const float2*)(ma + col);
            float2 mvb = *(const float2*)(mb + col);
            float e0 = __expf(acc[ntl][0] + mva.x);
            float e1 = __expf(acc[ntl][1] + mva.y);
            float e2 = __expf(acc[ntl][2] + mvb.x);
            float e3 = __expf(acc[ntl][3] + mvb.y);
            acc[ntl][0] = e0; acc[ntl][1] = e1;
            acc[ntl][2] = e2; acc[ntl][3] = e3;
            sa += e0 + e1; sb += e2 + e3;
        }
        sa += __shfl_xor_sync(0xffffffffu, sa, 1);
        sa += __shfl_xor_sync(0xffffffffu, sa, 2);
        sb += __shfl_xor_sync(0xffffffffu, sb, 1);
        sb += __shfl_xor_sync(0xffffffffu, sb, 2);
        if (t4 == 0) {
            rowsum[half * 96 + mt * 16 + gid]     = sa;
            rowsum[half * 96 + mt * 16 + 8 + gid] = sb;
        }
        __syncthreads();   // rowsum ready; prev chunk's PV reads of S done

        const float ia = 1.f / (rowsum[mt * 16 + gid]     + rowsum[96 + mt * 16 + gid]);
        const float ib = 1.f / (rowsum[mt * 16 + 8 + gid] + rowsum[96 + mt * 16 + 8 + gid]);
        float* s0 = S + (mt * 16 + gid) * SSTR;
        float* s1 = s0 + 8 * SSTR;
        #pragma unroll
        for (int ntl = 0; ntl < 18; ntl++) {
            const int col = (half * 18 + ntl) * 8 + t4 * 2;
            *(float2*)(s0 + col) =
                make_float2(tf32f(acc[ntl][0] * ia), tf32f(acc[ntl][1] * ia));
            *(float2*)(s1 + col) =
                make_float2(tf32f(acc[ntl][2] * ib), tf32f(acc[ntl][3] * ib));
        }
        __syncthreads();   // S (P matrix) complete

        // ---- O = P V  (3 balanced units/warp: (mt2, nt2, kq)) ----------
        #pragma unroll
        for (int u = 0; u < 3; u++) {
            const int uu  = wq + u * 12;
            const int mt2 = uu % 6;
            const int rest = uu / 6;
            const int nt2 = rest % 3;
            const int kq  = rest / 3;           // 0..1
            float acc2[4] = {0.f, 0.f, 0.f, 0.f};
            #pragma unroll 6
            for (int ks = 0; ks < 18; ks++) {
                const int k0 = kq * 144 + ks * 8;
                unsigned vb[2];
                vb[0] = __float_as_uint(Vs[(k0 + t4) * 26 + nt2 * 8 + gid]);
                vb[1] = __float_as_uint(Vs[(k0 + 4 + t4) * 26 + nt2 * 8 + gid]);
                const float* p0 = S + (mt2 * 16 + gid) * SSTR + k0 + t4;
                const float* p1 = p0 + 8 * SSTR;
                unsigned pa[4];
                pa[0] = __float_as_uint(p0[0]);
                pa[1] = __float_as_uint(p1[0]);
                pa[2] = __float_as_uint(p0[4]);
                pa[3] = __float_as_uint(p1[4]);
                mma_tf32(acc2, pa, vb);
            }
            float* pr = Pred + kq * (96 * 24);
            const int c = nt2 * 8 + t4 * 2;
            *(float2*)(pr + (mt2 * 16 + gid) * 24 + c) =
                make_float2(acc2[0], acc2[1]);
            *(float2*)(pr + (mt2 * 16 + 8 + gid) * 24 + c) =
                make_float2(acc2[2], acc2[3]);
        }
        __syncthreads();   // Pred complete

        // ---- reduce 2 k-halves, write O --------------------------------
        for (int e = tid; e < 96 * 24; e += 384) {
            const float s = Pred[e] + Pred[e + 2304];
            const int r = e / 24, c = e % 24;
            g_O[((size_t)b * SEQ + n0 + r) * CH + h * HD + c] = s;
        }
    }
}

// ===========================================================================
// Kernel 3: output projection on tensor cores (tf32 mma).
// grid = M/128, block = 512 (16 warps).  warp = (mt, nt-half of 6).
// smem: xs[128][100] + wsm[96][100]  (89600 B)
// ===========================================================================
__global__ __launch_bounds__(512) void proj_kernel(
    const float* __restrict__ proj_w,
    const float* __restrict__ proj_b,
    float* __restrict__ out)
{
    extern __shared__ float sm[];
    float* xs  = sm;               // [128][100]
    float* wsm = sm + 128 * 100;   // [96][100]

    const int tid = threadIdx.x;
    const int m0  = blockIdx.x * 128;

    for (int idx = tid; idx < 128 * 24; idx += 512) {
        int r = idx / 24, c4 = idx % 24;
        float4 v = *(const float4*)(g_O + (size_t)(m0 + r) * 96 + c4 * 4);
        v.x = tf32f(v.x); v.y = tf32f(v.y); v.z = tf32f(v.z); v.w = tf32f(v.w);
        *(float4*)(xs + r * 100 + c4 * 4) = v;
    }
    for (int idx = tid; idx < 96 * 96; idx += 512) {
        int n = idx / 96, k = idx % 96;
        wsm[n * 100 + k] = tf32f(proj_w[(size_t)n * 96 + k]);
    }
    __syncthreads();

    const int wq   = tid >> 5;
    const int lane = tid & 31;
    const int gid  = lane >> 2;
    const int t4   = lane & 3;
    const int mt   = wq & 7;
    const int nt0  = (wq >> 3) * 6;   // 12 nt total, halves of 6

    unsigned xa[12][4];
    {
        const float* x0 = xs + (mt * 16 + gid) * 100 + t4;
        const float* x1 = x0 + 8 * 100;
        #pragma unroll
        for (int ks = 0; ks < 12; ks++) {
            xa[ks][0] = __float_as_uint(x0[ks * 8]);
            xa[ks][1] = __float_as_uint(x1[ks * 8]);
            xa[ks][2] = __float_as_uint(x0[ks * 8 + 4]);
            xa[ks][3] = __float_as_uint(x1[ks * 8 + 4]);
        }
    }

    const int ma = m0 + mt * 16 + gid;
    const int mb = ma + 8;

    for (int nt = nt0; nt < nt0 + 6; ++nt) {
        float acc[4] = {0.f, 0.f, 0.f, 0.f};
        const float* wr = wsm + (nt * 8 + gid) * 100 + t4;
        #pragma unroll
        for (int ks = 0; ks < 12; ks++) {
            unsigned wb[2];
            wb[0] = __float_as_uint(wr[ks * 8]);
            wb[1] = __float_as_uint(wr[ks * 8 + 4]);
            mma_tf32(acc, xa[ks], wb);
        }
        const int col = nt * 8 + t4 * 2;
        const float b0 = proj_b[col], b1 = proj_b[col + 1];
        *(float2*)(out + (size_t)ma * 96 + col) =
            make_float2(acc[0] + b0, acc[1] + b1);
        *(float2*)(out + (size_t)mb * 96 + col) =
            make_float2(acc[2] + b0, acc[3] + b1);
    }
}

// ===========================================================================
extern "C" void kernel_launch(void* const* d_in, const int* in_sizes, int n_in,
                              void* d_out, int out_size)
{
    const float* x      = (const float*)d_in[0];
    const float* mask   = (const float*)d_in[1];
    const float* qkv_w  = (const float*)d_in[2];
    const float* qkv_b  = (const float*)d_in[3];
    const float* proj_w = (const float*)d_in[4];
    const float* proj_b = (const float*)d_in[5];
    float* out = (float*)d_out;

    const int smemQ = (128 * 100 + 288 * 100) * 4;  // 166400
    const int smemA = (SEQ * 25 + SEQ * 26 + 96 * SSTR + 2 * 96 * 24 + 192) * 4; // 191616
    const int smemP = (128 * 100 + 96 * 100) * 4;   // 89600

    cudaFuncSetAttribute(qkv_kernel,  cudaFuncAttributeMaxDynamicSharedMemorySize, smemQ);
    cudaFuncSetAttribute(attn_kernel, cudaFuncAttributeMaxDynamicSharedMemorySize, smemA);
    cudaFuncSetAttribute(proj_kernel, cudaFuncAttributeMaxDynamicSharedMemorySize, smemP);

    qkv_kernel<<<M_ROWS / 128, 512, smemQ>>>(x, qkv_w, qkv_b);
    attn_kernel<<<B_WIN * NH, 384, smemA>>>(mask);
    proj_kernel<<<M_ROWS / 128, 512, smemP>>>(proj_w, proj_b, out);
}

// round 12
// speedup vs baseline: 2.4520x; 1.1993x over previous
#include <cuda_runtime.h>
#include <math.h>

#define B_WIN 1024
#define SEQ   288
#define CH    96
#define NH    4
#define HD    24
#define NW    128
#define M_ROWS (B_WIN * SEQ)   // 294912

// ---------------- tf32 mma helpers ----------------------------------------
__device__ __forceinline__ unsigned tf32_of(float f) {
    unsigned r; asm("cvt.rna.tf32.f32 %0, %1;" : "=r"(r) : "f"(f)); return r;
}
__device__ __forceinline__ float tf32f(float f) {
    return __uint_as_float(tf32_of(f));
}
__device__ __forceinline__ void mma_tf32(float* d, const unsigned* a, const unsigned* b) {
    asm volatile("mma.sync.aligned.m16n8k8.row.col.f32.tf32.tf32.f32 "
        "{%0,%1,%2,%3}, {%4,%5,%6,%7}, {%8,%9}, {%0,%1,%2,%3};"
        : "+f"(d[0]), "+f"(d[1]), "+f"(d[2]), "+f"(d[3])
        : "r"(a[0]), "r"(a[1]), "r"(a[2]), "r"(a[3]), "r"(b[0]), "r"(b[1]));
}

// ---------------- scratch (device globals; no runtime allocation) ----------
__device__ float g_Q[B_WIN * NH * SEQ * HD];   // q pre-scaled, tf32-rounded
__device__ float g_K[B_WIN * NH * SEQ * HD];
__device__ float g_V[B_WIN * NH * SEQ * HD];
__device__ float g_O[M_ROWS * CH];

// ===========================================================================
// Kernel 1: QKV projection on tensor cores (tf32 mma).  Unchanged (271us).
// ===========================================================================
__global__ __launch_bounds__(512) void qkv_kernel(
    const float* __restrict__ x,
    const float* __restrict__ qkv_w,
    const float* __restrict__ qkv_b)
{
    extern __shared__ float sm[];
    float* xs  = sm;               // [128][100]
    float* wsm = sm + 128 * 100;   // [288][100]

    const int tid = threadIdx.x;
    const int m0  = blockIdx.x * 128;

    for (int idx = tid; idx < 128 * 24; idx += 512) {
        int r = idx / 24, c4 = idx % 24;
        float4 v = *(const float4*)(x + (size_t)(m0 + r) * 96 + c4 * 4);
        v.x = tf32f(v.x); v.y = tf32f(v.y); v.z = tf32f(v.z); v.w = tf32f(v.w);
        *(float4*)(xs + r * 100 + c4 * 4) = v;
    }
    for (int idx = tid; idx < 288 * 96; idx += 512) {
        int n = idx / 96, k = idx % 96;
        wsm[n * 100 + k] = tf32f(qkv_w[(size_t)n * 96 + k]);
    }
    __syncthreads();

    const int wq   = tid >> 5;
    const int lane = tid & 31;
    const int gid  = lane >> 2;
    const int t4   = lane & 3;
    const int mt   = wq & 7;
    const int nt0  = (wq >> 3) * 18;
    const float scale = 0.20412414523193154f;

    unsigned xa[12][4];
    {
        const float* x0 = xs + (mt * 16 + gid) * 100 + t4;
        const float* x1 = x0 + 8 * 100;
        #pragma unroll
        for (int ks = 0; ks < 12; ks++) {
            xa[ks][0] = __float_as_uint(x0[ks * 8]);
            xa[ks][1] = __float_as_uint(x1[ks * 8]);
            xa[ks][2] = __float_as_uint(x0[ks * 8 + 4]);
            xa[ks][3] = __float_as_uint(x1[ks * 8 + 4]);
        }
    }

    const int ma = m0 + mt * 16 + gid;
    const int mb = ma + 8;
    const int ba = ma / SEQ, na = ma % SEQ;
    const int bb = mb / SEQ, nb = mb % SEQ;

    for (int nt = nt0; nt < nt0 + 18; ++nt) {
        float acc[4] = {0.f, 0.f, 0.f, 0.f};
        const float* wr = wsm + (nt * 8 + gid) * 100 + t4;
        #pragma unroll
        for (int ks = 0; ks < 12; ks++) {
            unsigned wb[2];
            wb[0] = __float_as_uint(wr[ks * 8]);
            wb[1] = __float_as_uint(wr[ks * 8 + 4]);
            mma_tf32(acc, xa[ks], wb);
        }
        const int col = nt * 8 + t4 * 2;
        const int s   = col / 96;
        const int within = col - s * 96;
        const int h   = within / 24;
        const int dd  = within - h * 24;
        float* dst = (s == 0) ? g_Q : (s == 1) ? g_K : g_V;
        const float b0 = qkv_b[col], b1 = qkv_b[col + 1];
        float2 va = make_float2(acc[0] + b0, acc[1] + b1);
        float2 vb = make_float2(acc[2] + b0, acc[3] + b1);
        if (s == 0) { va.x *= scale; va.y *= scale; vb.x *= scale; vb.y *= scale; }
        va.x = tf32f(va.x); va.y = tf32f(va.y);
        vb.x = tf32f(vb.x); vb.y = tf32f(vb.y);
        *(float2*)(dst + (((size_t)ba * NH + h) * SEQ + na) * HD + dd) = va;
        *(float2*)(dst + (((size_t)bb * NH + h) * SEQ + nb) * HD + dd) = vb;
    }
}

// ===========================================================================
// Kernel 2: fused attention, NO S matrix in smem.
// grid = 4096 (b,h), block = 576 (18 warps).  warp = (mt 0..5, q 0..2):
// 16 rows x 96 cols of P held in registers end-to-end.
// c-frag -> a-frag conversion by warp shuffles; PV unit (mt, nt, kq=q).
// smem: Ks[288][25] + Vs[288][26] + Pred[3][96][24] + rowsum[3][96]
//     = 87552 B.  2 syncthreads per chunk.
// ===========================================================================
__global__ __launch_bounds__(576) void attn_kernel(const float* __restrict__ mask)
{
    extern __shared__ float sm[];
    float* Ks     = sm;                      // [288][25]
    float* Vs     = Ks + SEQ * 25;           // [288][26]
    float* Pred   = Vs + SEQ * 26;           // [3][96][24]
    float* rowsum = Pred + 3 * 96 * 24;      // [3][96]

    const int tid = threadIdx.x;
    const int bh  = blockIdx.x;
    const int b   = bh >> 2;
    const int h   = bh & 3;
    const int w   = b & (NW - 1);
    const size_t base = (size_t)bh * SEQ * HD;

    for (int idx = tid; idx < SEQ * HD; idx += 576) {
        const int r = idx / HD, c = idx % HD;
        Ks[r * 25 + c] = g_K[base + idx];    // already tf32-rounded by qkv
        Vs[r * 26 + c] = g_V[base + idx];
    }
    __syncthreads();

    const int wq   = tid >> 5;        // 0..17
    const int lane = tid & 31;
    const int gid  = lane >> 2;
    const int t4   = lane & 3;
    const int mt   = wq / 3;          // 0..5
    const int q    = wq % 3;          // col third 0..2
    const int c0   = q * 96;          // col base

    const unsigned FULL = 0xffffffffu;
    const int srcA = (lane & ~3) | (t4 >> 1);        // cols t4
    const int srcB = srcA + 2;                        // cols t4+4
    const bool odd = (t4 & 1);

    for (int qc = 0; qc < 3; ++qc) {
        const int n0 = qc * 96;

        // ---- QK: 12 col-tiles, acc in registers ------------------------
        unsigned qa[3][4];
        {
            const float* q0p = g_Q + base + (size_t)(n0 + mt * 16 + gid) * HD + t4;
            const float* q1p = q0p + 8 * HD;
            #pragma unroll
            for (int ks = 0; ks < 3; ks++) {
                qa[ks][0] = __float_as_uint(q0p[ks * 8]);
                qa[ks][1] = __float_as_uint(q1p[ks * 8]);
                qa[ks][2] = __float_as_uint(q0p[ks * 8 + 4]);
                qa[ks][3] = __float_as_uint(q1p[ks * 8 + 4]);
            }
        }
        float acc[12][4];
        #pragma unroll
        for (int j = 0; j < 12; j++) {
            acc[j][0] = acc[j][1] = acc[j][2] = acc[j][3] = 0.f;
            const float* kr = Ks + (c0 + j * 8 + gid) * 25 + t4;
            #pragma unroll
            for (int ks = 0; ks < 3; ks++) {
                unsigned kb[2];
                kb[0] = __float_as_uint(kr[ks * 8]);
                kb[1] = __float_as_uint(kr[ks * 8 + 4]);
                mma_tf32(acc[j], qa[ks], kb);
            }
        }

        // ---- mask + exp on register accumulators ----------------------
        const int rowa = n0 + mt * 16 + gid;
        const float* ma = mask + ((size_t)w * SEQ + rowa) * SEQ + c0;
        const float* mb = ma + 8 * SEQ;
        float sa = 0.f, sb = 0.f;
        #pragma unroll
        for (int j = 0; j < 12; j++) {
            const int cc = j * 8 + t4 * 2;
            float2 mva = *(const float2*)(ma + cc);
            float2 mvb = *(const float2*)(mb + cc);
            acc[j][0] = __expf(acc[j][0] + mva.x);
            acc[j][1] = __expf(acc[j][1] + mva.y);
            acc[j][2] = __expf(acc[j][2] + mvb.x);
            acc[j][3] = __expf(acc[j][3] + mvb.y);
            sa += acc[j][0] + acc[j][1];
            sb += acc[j][2] + acc[j][3];
        }
        sa += __shfl_xor_sync(FULL, sa, 1);
        sa += __shfl_xor_sync(FULL, sa, 2);
        sb += __shfl_xor_sync(FULL, sb, 1);
        sb += __shfl_xor_sync(FULL, sb, 2);
        if (t4 == 0) {
            rowsum[q * 96 + mt * 16 + gid]     = sa;
            rowsum[q * 96 + mt * 16 + 8 + gid] = sb;
        }
        __syncthreads();   // rowsum ready (also: prev chunk's Pred reads done)

        const int ra = mt * 16 + gid;
        const float ia = 1.f / (rowsum[ra] + rowsum[96 + ra] + rowsum[192 + ra]);
        const float ib = 1.f / (rowsum[ra + 8] + rowsum[96 + ra + 8] + rowsum[192 + ra + 8]);

        // normalize + tf32-round P in registers
        #pragma unroll
        for (int j = 0; j < 12; j++) {
            acc[j][0] = tf32f(acc[j][0] * ia);
            acc[j][1] = tf32f(acc[j][1] * ia);
            acc[j][2] = tf32f(acc[j][2] * ib);
            acc[j][3] = tf32f(acc[j][3] * ib);
        }

        // ---- O = P V: shuffle c-frag -> a-frag, PV over own k-range ----
        float acc2[3][4];
        #pragma unroll
        for (int nt = 0; nt < 3; nt++)
            acc2[nt][0] = acc2[nt][1] = acc2[nt][2] = acc2[nt][3] = 0.f;

        #pragma unroll
        for (int j = 0; j < 12; j++) {
            float s0  = __shfl_sync(FULL, acc[j][0], srcA);
            float s1  = __shfl_sync(FULL, acc[j][1], srcA);
            float s2  = __shfl_sync(FULL, acc[j][2], srcA);
            float s3  = __shfl_sync(FULL, acc[j][3], srcA);
            float s0b = __shfl_sync(FULL, acc[j][0], srcB);
            float s1b = __shfl_sync(FULL, acc[j][1], srcB);
            float s2b = __shfl_sync(FULL, acc[j][2], srcB);
            float s3b = __shfl_sync(FULL, acc[j][3], srcB);
            unsigned pa[4];
            pa[0] = __float_as_uint(odd ? s1  : s0);   // P[gid][c0+8j+t4]
            pa[1] = __float_as_uint(odd ? s3  : s2);   // P[gid+8][..]
            pa[2] = __float_as_uint(odd ? s1b : s0b);  // P[gid][..+4]
            pa[3] = __float_as_uint(odd ? s3b : s2b);  // P[gid+8][..+4]

            const int k0 = c0 + j * 8;
            #pragma unroll
            for (int nt = 0; nt < 3; nt++) {
                unsigned vb[2];
                vb[0] = __float_as_uint(Vs[(k0 + t4) * 26 + nt * 8 + gid]);
                vb[1] = __float_as_uint(Vs[(k0 + 4 + t4) * 26 + nt * 8 + gid]);
                mma_tf32(acc2[nt], pa, vb);
            }
        }
        float* pr = Pred + q * (96 * 24);
        #pragma unroll
        for (int nt = 0; nt < 3; nt++) {
            const int cc = nt * 8 + t4 * 2;
            *(float2*)(pr + ra * 24 + cc)       = make_float2(acc2[nt][0], acc2[nt][1]);
            *(float2*)(pr + (ra + 8) * 24 + cc) = make_float2(acc2[nt][2], acc2[nt][3]);
        }
        __syncthreads();   // Pred complete

        // ---- reduce 3 k-thirds, write O --------------------------------
        for (int e = tid; e < 96 * 24; e += 576) {
            const float s = Pred[e] + Pred[e + 2304] + Pred[e + 4608];
            const int r = e / 24, c = e % 24;
            g_O[((size_t)b * SEQ + n0 + r) * CH + h * HD + c] = s;
        }
    }
}

// ===========================================================================
// Kernel 3: output projection on tensor cores (tf32 mma).  Unchanged.
// ===========================================================================
__global__ __launch_bounds__(512) void proj_kernel(
    const float* __restrict__ proj_w,
    const float* __restrict__ proj_b,
    float* __restrict__ out)
{
    extern __shared__ float sm[];
    float* xs  = sm;               // [128][100]
    float* wsm = sm + 128 * 100;   // [96][100]

    const int tid = threadIdx.x;
    const int m0  = blockIdx.x * 128;

    for (int idx = tid; idx < 128 * 24; idx += 512) {
        int r = idx / 24, c4 = idx % 24;
        float4 v = *(const float4*)(g_O + (size_t)(m0 + r) * 96 + c4 * 4);
        v.x = tf32f(v.x); v.y = tf32f(v.y); v.z = tf32f(v.z); v.w = tf32f(v.w);
        *(float4*)(xs + r * 100 + c4 * 4) = v;
    }
    for (int idx = tid; idx < 96 * 96; idx += 512) {
        int n = idx / 96, k = idx % 96;
        wsm[n * 100 + k] = tf32f(proj_w[(size_t)n * 96 + k]);
    }
    __syncthreads();

    const int wq   = tid >> 5;
    const int lane = tid & 31;
    const int gid  = lane >> 2;
    const int t4   = lane & 3;
    const int mt   = wq & 7;
    const int nt0  = (wq >> 3) * 6;

    unsigned xa[12][4];
    {
        const float* x0 = xs + (mt * 16 + gid) * 100 + t4;
        const float* x1 = x0 + 8 * 100;
        #pragma unroll
        for (int ks = 0; ks < 12; ks++) {
            xa[ks][0] = __float_as_uint(x0[ks * 8]);
            xa[ks][1] = __float_as_uint(x1[ks * 8]);
            xa[ks][2] = __float_as_uint(x0[ks * 8 + 4]);
            xa[ks][3] = __float_as_uint(x1[ks * 8 + 4]);
        }
    }

    const int ma = m0 + mt * 16 + gid;
    const int mb = ma + 8;

    for (int nt = nt0; nt < nt0 + 6; ++nt) {
        float acc[4] = {0.f, 0.f, 0.f, 0.f};
        const float* wr = wsm + (nt * 8 + gid) * 100 + t4;
        #pragma unroll
        for (int ks = 0; ks < 12; ks++) {
            unsigned wb[2];
            wb[0] = __float_as_uint(wr[ks * 8]);
            wb[1] = __float_as_uint(wr[ks * 8 + 4]);
            mma_tf32(acc, xa[ks], wb);
        }
        const int col = nt * 8 + t4 * 2;
        const float b0 = proj_b[col], b1 = proj_b[col + 1];
        *(float2*)(out + (size_t)ma * 96 + col) =
            make_float2(acc[0] + b0, acc[1] + b1);
        *(float2*)(out + (size_t)mb * 96 + col) =
            make_float2(acc[2] + b0, acc[3] + b1);
    }
}

// ===========================================================================
extern "C" void kernel_launch(void* const* d_in, const int* in_sizes, int n_in,
                              void* d_out, int out_size)
{
    const float* x      = (const float*)d_in[0];
    const float* mask   = (const float*)d_in[1];
    const float* qkv_w  = (const float*)d_in[2];
    const float* qkv_b  = (const float*)d_in[3];
    const float* proj_w = (const float*)d_in[4];
    const float* proj_b = (const float*)d_in[5];
    float* out = (float*)d_out;

    const int smemQ = (128 * 100 + 288 * 100) * 4;            // 166400
    const int smemA = (SEQ * 25 + SEQ * 26 + 3 * 96 * 24 + 3 * 96) * 4; // 87552
    const int smemP = (128 * 100 + 96 * 100) * 4;             // 89600

    cudaFuncSetAttribute(qkv_kernel,  cudaFuncAttributeMaxDynamicSharedMemorySize, smemQ);
    cudaFuncSetAttribute(attn_kernel, cudaFuncAttributeMaxDynamicSharedMemorySize, smemA);
    cudaFuncSetAttribute(proj_kernel, cudaFuncAttributeMaxDynamicSharedMemorySize, smemP);

    qkv_kernel<<<M_ROWS / 128, 512, smemQ>>>(x, qkv_w, qkv_b);
    attn_kernel<<<B_WIN * NH, 576, smemA>>>(mask);
    proj_kernel<<<M_ROWS / 128, 512, smemP>>>(proj_w, proj_b, out);
}

// round 13
// speedup vs baseline: 2.9184x; 1.1902x over previous
#include <cuda_runtime.h>
#include <math.h>

#define B_WIN 1024
#define SEQ   288
#define CH    96
#define NH    4
#define HD    24
#define NW    128
#define M_ROWS (B_WIN * SEQ)   // 294912
#define NBH   (B_WIN * NH)     // 4096
#define NSM   148

// ---------------- tf32 mma helpers ----------------------------------------
__device__ __forceinline__ unsigned tf32_of(float f) {
    unsigned r; asm("cvt.rna.tf32.f32 %0, %1;" : "=r"(r) : "f"(f)); return r;
}
__device__ __forceinline__ float tf32f(float f) {
    return __uint_as_float(tf32_of(f));
}
__device__ __forceinline__ void mma_tf32(float* d, const unsigned* a, const unsigned* b) {
    asm volatile("mma.sync.aligned.m16n8k8.row.col.f32.tf32.tf32.f32 "
        "{%0,%1,%2,%3}, {%4,%5,%6,%7}, {%8,%9}, {%0,%1,%2,%3};"
        : "+f"(d[0]), "+f"(d[1]), "+f"(d[2]), "+f"(d[3])
        : "r"(a[0]), "r"(a[1]), "r"(a[2]), "r"(a[3]), "r"(b[0]), "r"(b[1]));
}
__device__ __forceinline__ unsigned smem_addr_u32(const void* p) {
    unsigned r;
    asm("{ .reg .u64 t; cvta.to.shared.u64 t, %1; cvt.u32.u64 %0, t; }"
        : "=r"(r) : "l"(p));
    return r;
}

// ---------------- scratch (device globals; no runtime allocation) ----------
__device__ float g_Q[B_WIN * NH * SEQ * HD];   // q pre-scaled, tf32-rounded
__device__ float g_K[B_WIN * NH * SEQ * HD];
__device__ float g_V[B_WIN * NH * SEQ * HD];
__device__ float g_O[M_ROWS * CH];

// ===========================================================================
// Kernel 1: QKV projection on tensor cores (tf32 mma), staged epilogue.
// grid = M/128, block = 512 (16 warps).  warp = (mt 0..7, half 0..1).
// 3 phases of 6 nt: mma -> stage in xs[128][100] -> coalesced float4 STG.
// ===========================================================================
__global__ __launch_bounds__(512) void qkv_kernel(
    const float* __restrict__ x,
    const float* __restrict__ qkv_w,
    const float* __restrict__ qkv_b)
{
    extern __shared__ float sm[];
    float* xs  = sm;               // [128][100]  (also the stage buffer)
    float* wsm = sm + 128 * 100;   // [288][100]

    const int tid = threadIdx.x;
    const int m0  = blockIdx.x * 128;

    for (int idx = tid; idx < 128 * 24; idx += 512) {
        int r = idx / 24, c4 = idx % 24;
        float4 v = *(const float4*)(x + (size_t)(m0 + r) * 96 + c4 * 4);
        v.x = tf32f(v.x); v.y = tf32f(v.y); v.z = tf32f(v.z); v.w = tf32f(v.w);
        *(float4*)(xs + r * 100 + c4 * 4) = v;
    }
    for (int idx = tid; idx < 288 * 24; idx += 512) {     // float4 W fill
        int n = idx / 24, k4 = idx % 24;
        float4 v = *(const float4*)(qkv_w + (size_t)n * 96 + k4 * 4);
        v.x = tf32f(v.x); v.y = tf32f(v.y); v.z = tf32f(v.z); v.w = tf32f(v.w);
        *(float4*)(wsm + n * 100 + k4 * 4) = v;
    }
    __syncthreads();

    const int wq   = tid >> 5;
    const int lane = tid & 31;
    const int gid  = lane >> 2;
    const int t4   = lane & 3;
    const int mt   = wq & 7;
    const int half = wq >> 3;
    const int nt0  = half * 18;
    const float scale = 0.20412414523193154f;

    unsigned xa[12][4];
    {
        const float* x0 = xs + (mt * 16 + gid) * 100 + t4;
        const float* x1 = x0 + 8 * 100;
        #pragma unroll
        for (int ks = 0; ks < 12; ks++) {
            xa[ks][0] = __float_as_uint(x0[ks * 8]);
            xa[ks][1] = __float_as_uint(x1[ks * 8]);
            xa[ks][2] = __float_as_uint(x0[ks * 8 + 4]);
            xa[ks][3] = __float_as_uint(x1[ks * 8 + 4]);
        }
    }

    const int rloc = mt * 16 + gid;   // local row 0..127

    for (int p = 0; p < 3; ++p) {
        float accp[6][4];
        #pragma unroll
        for (int l = 0; l < 6; l++) {
            accp[l][0] = accp[l][1] = accp[l][2] = accp[l][3] = 0.f;
            const int nt = nt0 + p * 6 + l;
            const float* wr = wsm + (nt * 8 + gid) * 100 + t4;
            #pragma unroll
            for (int ks = 0; ks < 12; ks++) {
                unsigned wb[2];
                wb[0] = __float_as_uint(wr[ks * 8]);
                wb[1] = __float_as_uint(wr[ks * 8 + 4]);
                mma_tf32(accp[l], xa[ks], wb);
            }
        }
        __syncthreads();   // all mma (and xa/wsm reads) done before stage STS

        #pragma unroll
        for (int l = 0; l < 6; l++) {
            const int nt  = nt0 + p * 6 + l;
            const int col = nt * 8 + t4 * 2;      // global output column
            const int s   = col / 96;
            const float b0 = qkv_b[col], b1 = qkv_b[col + 1];
            float2 va = make_float2(accp[l][0] + b0, accp[l][1] + b1);
            float2 vb = make_float2(accp[l][2] + b0, accp[l][3] + b1);
            if (s == 0) { va.x *= scale; va.y *= scale; vb.x *= scale; vb.y *= scale; }
            va.x = tf32f(va.x); va.y = tf32f(va.y);
            vb.x = tf32f(vb.x); vb.y = tf32f(vb.y);
            const int sc = half * 48 + l * 8 + t4 * 2;   // stage col 0..95
            *(float2*)(xs + rloc * 100 + sc)       = va;
            *(float2*)(xs + (rloc + 8) * 100 + sc) = vb;
        }
        __syncthreads();   // stage complete

        // coalesced writer: 128 rows x 24 float4
        for (int i2 = tid; i2 < 128 * 24; i2 += 512) {
            const int r  = i2 / 24, c4 = i2 % 24;
            float4 v = *(const float4*)(xs + r * 100 + c4 * 4);
            const int gcol = (c4 / 12) * 144 + p * 48 + (c4 % 12) * 4;
            const int s    = gcol / 96;
            const int w_in = gcol - s * 96;
            const int h    = w_in / 24;
            const int dd   = w_in - h * 24;       // multiple of 4
            const int m = m0 + r;
            const int b = m / SEQ, n = m % SEQ;
            float* dst = (s == 0) ? g_Q : (s == 1) ? g_K : g_V;
            *(float4*)(dst + (((size_t)b * NH + h) * SEQ + n) * HD + dd) = v;
        }
        // next phase's post-mma barrier orders writer completion vs re-staging
    }
}

// ===========================================================================
// Kernel 2: persistent fused attention, double-buffered K/V via cp.async.
// grid = 148, block = 576 (18 warps).  Each block walks bh = bid, bid+148, ...
// warp = (mt 0..5, q 0..2): 16 rows x 96 cols of P in registers end-to-end.
// smem per buffer: Ks[288][28] + Vs[288][26]; x2 buffers + Pred[3][96][24]
//   + rowsum[3][96] = 153216 B.
// ===========================================================================
__device__ __forceinline__ void prefetch_kv(float* smbase, int buf, int bh, int tid)
{
    float* Ks = smbase + buf * 15552;
    float* Vs = Ks + 288 * 28;
    const size_t base = (size_t)bh * SEQ * HD;
    const float* gk = g_K + base;
    const float* gv = g_V + base;
    for (int i = tid; i < SEQ * 6; i += 576) {         // K: 16B ops
        int r = i / 6, c4 = i % 6;
        unsigned d = smem_addr_u32(Ks + r * 28 + c4 * 4);
        asm volatile("cp.async.ca.shared.global [%0], [%1], 16;"
                     :: "r"(d), "l"(gk + r * 24 + c4 * 4));
    }
    for (int i = tid; i < SEQ * 12; i += 576) {        // V: 8B ops
        int r = i / 12, c2 = i % 12;
        unsigned d = smem_addr_u32(Vs + r * 26 + c2 * 2);
        asm volatile("cp.async.ca.shared.global [%0], [%1], 8;"
                     :: "r"(d), "l"(gv + r * 24 + c2 * 2));
    }
}

__global__ __launch_bounds__(576) void attn_kernel(const float* __restrict__ mask)
{
    extern __shared__ float sm[];
    float* Pred   = sm + 2 * 15552;          // [3][96][24]
    float* rowsum = Pred + 3 * 96 * 24;      // [3][96]

    const int tid  = threadIdx.x;
    const int wq   = tid >> 5;        // 0..17
    const int lane = tid & 31;
    const int gid  = lane >> 2;
    const int t4   = lane & 3;
    const int mt   = wq / 3;          // 0..5
    const int q    = wq % 3;          // col third
    const int c0   = q * 96;

    const unsigned FULL = 0xffffffffu;
    const int srcA = (lane & ~3) | (t4 >> 1);
    const int srcB = srcA + 2;
    const bool odd = (t4 & 1);

    int bh  = blockIdx.x;
    int cur = 0;
    if (bh < NBH) prefetch_kv(sm, cur, bh, tid);
    asm volatile("cp.async.commit_group;");

    for (; bh < NBH; bh += NSM) {
        const int nbh = bh + NSM;
        if (nbh < NBH) {
            prefetch_kv(sm, cur ^ 1, nbh, tid);
            asm volatile("cp.async.commit_group;");
            asm volatile("cp.async.wait_group 1;");
        } else {
            asm volatile("cp.async.wait_group 0;");
        }
        __syncthreads();   // current buffer visible to all

        float* Ks = sm + cur * 15552;
        float* Vs = Ks + 288 * 28;
        const int b = bh >> 2;
        const int h = bh & 3;
        const int w = b & (NW - 1);
        const size_t base = (size_t)bh * SEQ * HD;

        for (int qc = 0; qc < 3; ++qc) {
            const int n0 = qc * 96;

            // ---- QK: 12 col-tiles, acc in registers --------------------
            unsigned qa[3][4];
            {
                const float* q0p = g_Q + base + (size_t)(n0 + mt * 16 + gid) * HD + t4;
                const float* q1p = q0p + 8 * HD;
                #pragma unroll
                for (int ks = 0; ks < 3; ks++) {
                    qa[ks][0] = __float_as_uint(q0p[ks * 8]);
                    qa[ks][1] = __float_as_uint(q1p[ks * 8]);
                    qa[ks][2] = __float_as_uint(q0p[ks * 8 + 4]);
                    qa[ks][3] = __float_as_uint(q1p[ks * 8 + 4]);
                }
            }
            float acc[12][4];
            #pragma unroll
            for (int j = 0; j < 12; j++) {
                acc[j][0] = acc[j][1] = acc[j][2] = acc[j][3] = 0.f;
                const float* kr = Ks + (c0 + j * 8 + gid) * 28 + t4;
                #pragma unroll
                for (int ks = 0; ks < 3; ks++) {
                    unsigned kb[2];
                    kb[0] = __float_as_uint(kr[ks * 8]);
                    kb[1] = __float_as_uint(kr[ks * 8 + 4]);
                    mma_tf32(acc[j], qa[ks], kb);
                }
            }

            // ---- mask + exp on register accumulators ------------------
            const int rowa = n0 + mt * 16 + gid;
            const float* ma = mask + ((size_t)w * SEQ + rowa) * SEQ + c0;
            const float* mb = ma + 8 * SEQ;
            float sa = 0.f, sb = 0.f;
            #pragma unroll
            for (int j = 0; j < 12; j++) {
                const int cc = j * 8 + t4 * 2;
                float2 mva = *(const float2*)(ma + cc);
                float2 mvb = *(const float2*)(mb + cc);
                acc[j][0] = __expf(acc[j][0] + mva.x);
                acc[j][1] = __expf(acc[j][1] + mva.y);
                acc[j][2] = __expf(acc[j][2] + mvb.x);
                acc[j][3] = __expf(acc[j][3] + mvb.y);
                sa += acc[j][0] + acc[j][1];
                sb += acc[j][2] + acc[j][3];
            }
            sa += __shfl_xor_sync(FULL, sa, 1);
            sa += __shfl_xor_sync(FULL, sa, 2);
            sb += __shfl_xor_sync(FULL, sb, 1);
            sb += __shfl_xor_sync(FULL, sb, 2);
            if (t4 == 0) {
                rowsum[q * 96 + mt * 16 + gid]     = sa;
                rowsum[q * 96 + mt * 16 + 8 + gid] = sb;
            }
            __syncthreads();   // rowsum ready; prev Pred reads done

            const int ra = mt * 16 + gid;
            const float ia = 1.f / (rowsum[ra] + rowsum[96 + ra] + rowsum[192 + ra]);
            const float ib = 1.f / (rowsum[ra + 8] + rowsum[96 + ra + 8] + rowsum[192 + ra + 8]);

            #pragma unroll
            for (int j = 0; j < 12; j++) {
                acc[j][0] = tf32f(acc[j][0] * ia);
                acc[j][1] = tf32f(acc[j][1] * ia);
                acc[j][2] = tf32f(acc[j][2] * ib);
                acc[j][3] = tf32f(acc[j][3] * ib);
            }

            // ---- O = P V via shuffle c->a frag conversion --------------
            float acc2[3][4];
            #pragma unroll
            for (int nt = 0; nt < 3; nt++)
                acc2[nt][0] = acc2[nt][1] = acc2[nt][2] = acc2[nt][3] = 0.f;

            #pragma unroll
            for (int j = 0; j < 12; j++) {
                float s0  = __shfl_sync(FULL, acc[j][0], srcA);
                float s1  = __shfl_sync(FULL, acc[j][1], srcA);
                float s2  = __shfl_sync(FULL, acc[j][2], srcA);
                float s3  = __shfl_sync(FULL, acc[j][3], srcA);
                float s0b = __shfl_sync(FULL, acc[j][0], srcB);
                float s1b = __shfl_sync(FULL, acc[j][1], srcB);
                float s2b = __shfl_sync(FULL, acc[j][2], srcB);
                float s3b = __shfl_sync(FULL, acc[j][3], srcB);
                unsigned pa[4];
                pa[0] = __float_as_uint(odd ? s1  : s0);
                pa[1] = __float_as_uint(odd ? s3  : s2);
                pa[2] = __float_as_uint(odd ? s1b : s0b);
                pa[3] = __float_as_uint(odd ? s3b : s2b);

                const int k0 = c0 + j * 8;
                #pragma unroll
                for (int nt = 0; nt < 3; nt++) {
                    unsigned vb[2];
                    vb[0] = __float_as_uint(Vs[(k0 + t4) * 26 + nt * 8 + gid]);
                    vb[1] = __float_as_uint(Vs[(k0 + 4 + t4) * 26 + nt * 8 + gid]);
                    mma_tf32(acc2[nt], pa, vb);
                }
            }
            float* pr = Pred + q * (96 * 24);
            #pragma unroll
            for (int nt = 0; nt < 3; nt++) {
                const int cc = nt * 8 + t4 * 2;
                *(float2*)(pr + ra * 24 + cc)       = make_float2(acc2[nt][0], acc2[nt][1]);
                *(float2*)(pr + (ra + 8) * 24 + cc) = make_float2(acc2[nt][2], acc2[nt][3]);
            }
            __syncthreads();   // Pred complete

            for (int e = tid; e < 96 * 24; e += 576) {
                const float s = Pred[e] + Pred[e + 2304] + Pred[e + 4608];
                const int r = e / 24, c = e % 24;
                g_O[((size_t)b * SEQ + n0 + r) * CH + h * HD + c] = s;
            }
        }
        __syncthreads();   // all reads of cur done before it becomes prefetch target
        cur ^= 1;
    }
}

// ===========================================================================
// Kernel 3: output projection on tensor cores, staged epilogue.
// grid = M/128, block = 512.  stage = xs[128][100]; coalesced float4 out.
// ===========================================================================
__global__ __launch_bounds__(512) void proj_kernel(
    const float* __restrict__ proj_w,
    const float* __restrict__ proj_b,
    float* __restrict__ out)
{
    extern __shared__ float sm[];
    float* xs  = sm;               // [128][100]  (also the stage)
    float* wsm = sm + 128 * 100;   // [96][100]

    const int tid = threadIdx.x;
    const int m0  = blockIdx.x * 128;

    for (int idx = tid; idx < 128 * 24; idx += 512) {
        int r = idx / 24, c4 = idx % 24;
        float4 v = *(const float4*)(g_O + (size_t)(m0 + r) * 96 + c4 * 4);
        v.x = tf32f(v.x); v.y = tf32f(v.y); v.z = tf32f(v.z); v.w = tf32f(v.w);
        *(float4*)(xs + r * 100 + c4 * 4) = v;
    }
    for (int idx = tid; idx < 96 * 24; idx += 512) {      // float4 W fill
        int n = idx / 24, k4 = idx % 24;
        float4 v = *(const float4*)(proj_w + (size_t)n * 96 + k4 * 4);
        v.x = tf32f(v.x); v.y = tf32f(v.y); v.z = tf32f(v.z); v.w = tf32f(v.w);
        *(float4*)(wsm + n * 100 + k4 * 4) = v;
    }
    __syncthreads();

    const int wq   = tid >> 5;
    const int lane = tid & 31;
    const int gid  = lane >> 2;
    const int t4   = lane & 3;
    const int mt   = wq & 7;
    const int nt0  = (wq >> 3) * 6;

    unsigned xa[12][4];
    {
        const float* x0 = xs + (mt * 16 + gid) * 100 + t4;
        const float* x1 = x0 + 8 * 100;
        #pragma unroll
        for (int ks = 0; ks < 12; ks++) {
            xa[ks][0] = __float_as_uint(x0[ks * 8]);
            xa[ks][1] = __float_as_uint(x1[ks * 8]);
            xa[ks][2] = __float_as_uint(x0[ks * 8 + 4]);
            xa[ks][3] = __float_as_uint(x1[ks * 8 + 4]);
        }
    }

    float accp[6][4];
    #pragma unroll
    for (int l = 0; l < 6; l++) {
        accp[l][0] = accp[l][1] = accp[l][2] = accp[l][3] = 0.f;
        const float* wr = wsm + ((nt0 + l) * 8 + gid) * 100 + t4;
        #pragma unroll
        for (int ks = 0; ks < 12; ks++) {
            unsigned wb[2];
            wb[0] = __float_as_uint(wr[ks * 8]);
            wb[1] = __float_as_uint(wr[ks * 8 + 4]);
            mma_tf32(accp[l], xa[ks], wb);
        }
    }
    __syncthreads();   // all mma/xs/wsm reads done

    const int rloc = mt * 16 + gid;
    #pragma unroll
    for (int l = 0; l < 6; l++) {
        const int col = (nt0 + l) * 8 + t4 * 2;   // 0..95, unique per warp-half
        const float b0 = proj_b[col], b1 = proj_b[col + 1];
        *(float2*)(xs + rloc * 100 + col) =
            make_float2(accp[l][0] + b0, accp[l][1] + b1);
        *(float2*)(xs + (rloc + 8) * 100 + col) =
            make_float2(accp[l][2] + b0, accp[l][3] + b1);
    }
    __syncthreads();

    for (int i2 = tid; i2 < 128 * 24; i2 += 512) {
        const int r = i2 / 24, c4 = i2 % 24;
        float4 v = *(const float4*)(xs + r * 100 + c4 * 4);
        *(float4*)(out + (size_t)(m0 + r) * 96 + c4 * 4) = v;
    }
}

// ===========================================================================
extern "C" void kernel_launch(void* const* d_in, const int* in_sizes, int n_in,
                              void* d_out, int out_size)
{
    const float* x      = (const float*)d_in[0];
    const float* mask   = (const float*)d_in[1];
    const float* qkv_w  = (const float*)d_in[2];
    const float* qkv_b  = (const float*)d_in[3];
    const float* proj_w = (const float*)d_in[4];
    const float* proj_b = (const float*)d_in[5];
    float* out = (float*)d_out;

    const int smemQ = (128 * 100 + 288 * 100) * 4;                     // 166400
    const int smemA = (2 * 15552 + 3 * 96 * 24 + 3 * 96) * 4;          // 153216
    const int smemP = (128 * 100 + 96 * 100) * 4;                      // 89600

    cudaFuncSetAttribute(qkv_kernel,  cudaFuncAttributeMaxDynamicSharedMemorySize, smemQ);
    cudaFuncSetAttribute(attn_kernel, cudaFuncAttributeMaxDynamicSharedMemorySize, smemA);
    cudaFuncSetAttribute(proj_kernel, cudaFuncAttributeMaxDynamicSharedMemorySize, smemP);

    qkv_kernel<<<M_ROWS / 128, 512, smemQ>>>(x, qkv_w, qkv_b);
    attn_kernel<<<NSM, 576, smemA>>>(mask);
    proj_kernel<<<M_ROWS / 128, 512, smemP>>>(proj_w, proj_b, out);
}

// round 14
// speedup vs baseline: 3.2978x; 1.1300x over previous
#include <cuda_runtime.h>
#include <math.h>

#define B_WIN 1024
#define SEQ   288
#define CH    96
#define NH    4
#define HD    24
#define NW    128
#define M_ROWS (B_WIN * SEQ)   // 294912
#define NBH   (B_WIN * NH)     // 4096
#define NSM   148

// ---------------- tf32 mma helpers ----------------------------------------
__device__ __forceinline__ unsigned tf32_of(float f) {
    unsigned r; asm("cvt.rna.tf32.f32 %0, %1;" : "=r"(r) : "f"(f)); return r;
}
__device__ __forceinline__ float tf32f(float f) {
    return __uint_as_float(tf32_of(f));
}
__device__ __forceinline__ void mma_tf32(float* d, const unsigned* a, const unsigned* b) {
    asm volatile("mma.sync.aligned.m16n8k8.row.col.f32.tf32.tf32.f32 "
        "{%0,%1,%2,%3}, {%4,%5,%6,%7}, {%8,%9}, {%0,%1,%2,%3};"
        : "+f"(d[0]), "+f"(d[1]), "+f"(d[2]), "+f"(d[3])
        : "r"(a[0]), "r"(a[1]), "r"(a[2]), "r"(a[3]), "r"(b[0]), "r"(b[1]));
}
__device__ __forceinline__ unsigned smem_addr_u32(const void* p) {
    unsigned r;
    asm("{ .reg .u64 t; cvta.to.shared.u64 t, %1; cvt.u32.u64 %0, t; }"
        : "=r"(r) : "l"(p));
    return r;
}
__device__ __forceinline__ void bar_named(int id, int nthreads) {
    asm volatile("bar.sync %0, %1;" :: "r"(id), "r"(nthreads) : "memory");
}

// ---------------- scratch (device globals; no runtime allocation) ----------
__device__ float g_Q[B_WIN * NH * SEQ * HD];   // q pre-scaled, tf32-rounded
__device__ float g_K[B_WIN * NH * SEQ * HD];
__device__ float g_V[B_WIN * NH * SEQ * HD];
__device__ float g_O[M_ROWS * CH];

// ===========================================================================
// Kernel 1: QKV projection on tensor cores (tf32 mma).  R12 version (270us).
// ===========================================================================
__global__ __launch_bounds__(512) void qkv_kernel(
    const float* __restrict__ x,
    const float* __restrict__ qkv_w,
    const float* __restrict__ qkv_b)
{
    extern __shared__ float sm[];
    float* xs  = sm;               // [128][100]
    float* wsm = sm + 128 * 100;   // [288][100]

    const int tid = threadIdx.x;
    const int m0  = blockIdx.x * 128;

    for (int idx = tid; idx < 128 * 24; idx += 512) {
        int r = idx / 24, c4 = idx % 24;
        float4 v = *(const float4*)(x + (size_t)(m0 + r) * 96 + c4 * 4);
        v.x = tf32f(v.x); v.y = tf32f(v.y); v.z = tf32f(v.z); v.w = tf32f(v.w);
        *(float4*)(xs + r * 100 + c4 * 4) = v;
    }
    for (int idx = tid; idx < 288 * 24; idx += 512) {
        int n = idx / 24, k4 = idx % 24;
        float4 v = *(const float4*)(qkv_w + (size_t)n * 96 + k4 * 4);
        v.x = tf32f(v.x); v.y = tf32f(v.y); v.z = tf32f(v.z); v.w = tf32f(v.w);
        *(float4*)(wsm + n * 100 + k4 * 4) = v;
    }
    __syncthreads();

    const int wq   = tid >> 5;
    const int lane = tid & 31;
    const int gid  = lane >> 2;
    const int t4   = lane & 3;
    const int mt   = wq & 7;
    const int nt0  = (wq >> 3) * 18;
    const float scale = 0.20412414523193154f;

    unsigned xa[12][4];
    {
        const float* x0 = xs + (mt * 16 + gid) * 100 + t4;
        const float* x1 = x0 + 8 * 100;
        #pragma unroll
        for (int ks = 0; ks < 12; ks++) {
            xa[ks][0] = __float_as_uint(x0[ks * 8]);
            xa[ks][1] = __float_as_uint(x1[ks * 8]);
            xa[ks][2] = __float_as_uint(x0[ks * 8 + 4]);
            xa[ks][3] = __float_as_uint(x1[ks * 8 + 4]);
        }
    }

    const int ma = m0 + mt * 16 + gid;
    const int mb = ma + 8;
    const int ba = ma / SEQ, na = ma % SEQ;
    const int bb = mb / SEQ, nb = mb % SEQ;

    for (int nt = nt0; nt < nt0 + 18; ++nt) {
        float acc[4] = {0.f, 0.f, 0.f, 0.f};
        const float* wr = wsm + (nt * 8 + gid) * 100 + t4;
        #pragma unroll
        for (int ks = 0; ks < 12; ks++) {
            unsigned wb[2];
            wb[0] = __float_as_uint(wr[ks * 8]);
            wb[1] = __float_as_uint(wr[ks * 8 + 4]);
            mma_tf32(acc, xa[ks], wb);
        }
        const int col = nt * 8 + t4 * 2;
        const int s   = col / 96;
        const int within = col - s * 96;
        const int h   = within / 24;
        const int dd  = within - h * 24;
        float* dst = (s == 0) ? g_Q : (s == 1) ? g_K : g_V;
        const float b0 = qkv_b[col], b1 = qkv_b[col + 1];
        float2 va = make_float2(acc[0] + b0, acc[1] + b1);
        float2 vb = make_float2(acc[2] + b0, acc[3] + b1);
        if (s == 0) { va.x *= scale; va.y *= scale; vb.x *= scale; vb.y *= scale; }
        va.x = tf32f(va.x); va.y = tf32f(va.y);
        vb.x = tf32f(vb.x); vb.y = tf32f(vb.y);
        *(float2*)(dst + (((size_t)ba * NH + h) * SEQ + na) * HD + dd) = va;
        *(float2*)(dst + (((size_t)bb * NH + h) * SEQ + nb) * HD + dd) = vb;
    }
}

// ===========================================================================
// Kernel 2: persistent fused attention, double-buffered K/V via cp.async.
// grid = 148, block = 576 (18 warps).  warp = (mt 0..5, q 0..2).
// In-chunk syncs are NAMED barriers over the 3-warp mt group (id 1+mt, 96
// threads) — the 6 groups pipeline independently.  One full barrier per
// bh-iter protects buffer swap.
// smem: 2 x (Ks[288][28] + Vs[288][26]) + Pred[3][96][24] + rowsum[3][96]
//     = 153216 B.
// ===========================================================================
__device__ __forceinline__ void prefetch_kv(float* smbase, int buf, int bh, int tid)
{
    float* Ks = smbase + buf * 15552;
    float* Vs = Ks + 288 * 28;
    const size_t base = (size_t)bh * SEQ * HD;
    const float* gk = g_K + base;
    const float* gv = g_V + base;
    for (int i = tid; i < SEQ * 6; i += 576) {         // K: 16B ops
        int r = i / 6, c4 = i % 6;
        unsigned d = smem_addr_u32(Ks + r * 28 + c4 * 4);
        asm volatile("cp.async.ca.shared.global [%0], [%1], 16;"
                     :: "r"(d), "l"(gk + r * 24 + c4 * 4));
    }
    for (int i = tid; i < SEQ * 12; i += 576) {        // V: 8B ops
        int r = i / 12, c2 = i % 12;
        unsigned d = smem_addr_u32(Vs + r * 26 + c2 * 2);
        asm volatile("cp.async.ca.shared.global [%0], [%1], 8;"
                     :: "r"(d), "l"(gv + r * 24 + c2 * 2));
    }
}

__global__ __launch_bounds__(576) void attn_kernel(const float* __restrict__ mask)
{
    extern __shared__ float sm[];
    float* Pred   = sm + 2 * 15552;          // [3][96][24]
    float* rowsum = Pred + 3 * 96 * 24;      // [3][96]

    const int tid  = threadIdx.x;
    const int wq   = tid >> 5;        // 0..17
    const int lane = tid & 31;
    const int gid  = lane >> 2;
    const int t4   = lane & 3;
    const int mt   = wq / 3;          // 0..5  (group)
    const int q    = wq % 3;          // col third
    const int c0   = q * 96;
    const int barid = 1 + mt;         // named barrier per group
    const int gtid  = q * 32 + lane;  // 0..95 within group

    const unsigned FULL = 0xffffffffu;
    const int srcA = (lane & ~3) | (t4 >> 1);
    const int srcB = srcA + 2;
    const bool odd = (t4 & 1);

    int bh  = blockIdx.x;
    int cur = 0;
    if (bh < NBH) prefetch_kv(sm, cur, bh, tid);
    asm volatile("cp.async.commit_group;");

    for (; bh < NBH; bh += NSM) {
        const int nbh = bh + NSM;
        if (nbh < NBH) {
            prefetch_kv(sm, cur ^ 1, nbh, tid);
            asm volatile("cp.async.commit_group;");
            asm volatile("cp.async.wait_group 1;");
        } else {
            asm volatile("cp.async.wait_group 0;");
        }
        __syncthreads();   // current buffer visible to all

        float* Ks = sm + cur * 15552;
        float* Vs = Ks + 288 * 28;
        const int b = bh >> 2;
        const int h = bh & 3;
        const int w = b & (NW - 1);
        const size_t base = (size_t)bh * SEQ * HD;

        for (int qc = 0; qc < 3; ++qc) {
            const int n0 = qc * 96;

            // ---- QK: 12 col-tiles, acc in registers --------------------
            unsigned qa[3][4];
            {
                const float* q0p = g_Q + base + (size_t)(n0 + mt * 16 + gid) * HD + t4;
                const float* q1p = q0p + 8 * HD;
                #pragma unroll
                for (int ks = 0; ks < 3; ks++) {
                    qa[ks][0] = __float_as_uint(q0p[ks * 8]);
                    qa[ks][1] = __float_as_uint(q1p[ks * 8]);
                    qa[ks][2] = __float_as_uint(q0p[ks * 8 + 4]);
                    qa[ks][3] = __float_as_uint(q1p[ks * 8 + 4]);
                }
            }
            float acc[12][4];
            #pragma unroll
            for (int j = 0; j < 12; j++) {
                acc[j][0] = acc[j][1] = acc[j][2] = acc[j][3] = 0.f;
                const float* kr = Ks + (c0 + j * 8 + gid) * 28 + t4;
                #pragma unroll
                for (int ks = 0; ks < 3; ks++) {
                    unsigned kb[2];
                    kb[0] = __float_as_uint(kr[ks * 8]);
                    kb[1] = __float_as_uint(kr[ks * 8 + 4]);
                    mma_tf32(acc[j], qa[ks], kb);
                }
            }

            // ---- mask + exp on register accumulators ------------------
            const int rowa = n0 + mt * 16 + gid;
            const float* ma = mask + ((size_t)w * SEQ + rowa) * SEQ + c0;
            const float* mb = ma + 8 * SEQ;
            float sa = 0.f, sb = 0.f;
            #pragma unroll
            for (int j = 0; j < 12; j++) {
                const int cc = j * 8 + t4 * 2;
                float2 mva = *(const float2*)(ma + cc);
                float2 mvb = *(const float2*)(mb + cc);
                acc[j][0] = __expf(acc[j][0] + mva.x);
                acc[j][1] = __expf(acc[j][1] + mva.y);
                acc[j][2] = __expf(acc[j][2] + mvb.x);
                acc[j][3] = __expf(acc[j][3] + mvb.y);
                sa += acc[j][0] + acc[j][1];
                sb += acc[j][2] + acc[j][3];
            }
            sa += __shfl_xor_sync(FULL, sa, 1);
            sa += __shfl_xor_sync(FULL, sa, 2);
            sb += __shfl_xor_sync(FULL, sb, 1);
            sb += __shfl_xor_sync(FULL, sb, 2);
            if (t4 == 0) {
                rowsum[q * 96 + mt * 16 + gid]     = sa;
                rowsum[q * 96 + mt * 16 + 8 + gid] = sb;
            }
            bar_named(barid, 96);   // group's rowsum exchange

            const int ra = mt * 16 + gid;
            const float ia = 1.f / (rowsum[ra] + rowsum[96 + ra] + rowsum[192 + ra]);
            const float ib = 1.f / (rowsum[ra + 8] + rowsum[96 + ra + 8] + rowsum[192 + ra + 8]);

            #pragma unroll
            for (int j = 0; j < 12; j++) {
                acc[j][0] = tf32f(acc[j][0] * ia);
                acc[j][1] = tf32f(acc[j][1] * ia);
                acc[j][2] = tf32f(acc[j][2] * ib);
                acc[j][3] = tf32f(acc[j][3] * ib);
            }

            // ---- O = P V via shuffle c->a frag conversion --------------
            float acc2[3][4];
            #pragma unroll
            for (int nt = 0; nt < 3; nt++)
                acc2[nt][0] = acc2[nt][1] = acc2[nt][2] = acc2[nt][3] = 0.f;

            #pragma unroll
            for (int j = 0; j < 12; j++) {
                float s0  = __shfl_sync(FULL, acc[j][0], srcA);
                float s1  = __shfl_sync(FULL, acc[j][1], srcA);
                float s2  = __shfl_sync(FULL, acc[j][2], srcA);
                float s3  = __shfl_sync(FULL, acc[j][3], srcA);
                float s0b = __shfl_sync(FULL, acc[j][0], srcB);
                float s1b = __shfl_sync(FULL, acc[j][1], srcB);
                float s2b = __shfl_sync(FULL, acc[j][2], srcB);
                float s3b = __shfl_sync(FULL, acc[j][3], srcB);
                unsigned pa[4];
                pa[0] = __float_as_uint(odd ? s1  : s0);
                pa[1] = __float_as_uint(odd ? s3  : s2);
                pa[2] = __float_as_uint(odd ? s1b : s0b);
                pa[3] = __float_as_uint(odd ? s3b : s2b);

                const int k0 = c0 + j * 8;
                #pragma unroll
                for (int nt = 0; nt < 3; nt++) {
                    unsigned vb[2];
                    vb[0] = __float_as_uint(Vs[(k0 + t4) * 26 + nt * 8 + gid]);
                    vb[1] = __float_as_uint(Vs[(k0 + 4 + t4) * 26 + nt * 8 + gid]);
                    mma_tf32(acc2[nt], pa, vb);
                }
            }
            float* pr = Pred + q * (96 * 24);
            #pragma unroll
            for (int nt = 0; nt < 3; nt++) {
                const int cc = nt * 8 + t4 * 2;
                *(float2*)(pr + ra * 24 + cc)       = make_float2(acc2[nt][0], acc2[nt][1]);
                *(float2*)(pr + (ra + 8) * 24 + cc) = make_float2(acc2[nt][2], acc2[nt][3]);
            }
            bar_named(barid, 96);   // group's Pred complete

            // ---- group writer: rows mt*16..mt*16+15, 3-way reduce ------
            #pragma unroll
            for (int e = gtid; e < 16 * 24; e += 96) {
                const int rl = e / 24, c = e % 24;
                const int ro = mt * 16 + rl;
                const float s = Pred[ro * 24 + c] + Pred[2304 + ro * 24 + c]
                              + Pred[4608 + ro * 24 + c];
                g_O[((size_t)b * SEQ + n0 + ro) * CH + h * HD + c] = s;
            }
            // next chunk: this group's Pred/rowsum regions are private to
            // the group, so its next named barrier provides the ordering.
        }
        __syncthreads();   // all reads of cur done before it becomes prefetch target
        cur ^= 1;
    }
}

// ===========================================================================
// Kernel 3: output projection on tensor cores, staged epilogue (R13, ~88us).
// ===========================================================================
__global__ __launch_bounds__(512) void proj_kernel(
    const float* __restrict__ proj_w,
    const float* __restrict__ proj_b,
    float* __restrict__ out)
{
    extern __shared__ float sm[];
    float* xs  = sm;               // [128][100]  (also the stage)
    float* wsm = sm + 128 * 100;   // [96][100]

    const int tid = threadIdx.x;
    const int m0  = blockIdx.x * 128;

    for (int idx = tid; idx < 128 * 24; idx += 512) {
        int r = idx / 24, c4 = idx % 24;
        float4 v = *(const float4*)(g_O + (size_t)(m0 + r) * 96 + c4 * 4);
        v.x = tf32f(v.x); v.y = tf32f(v.y); v.z = tf32f(v.z); v.w = tf32f(v.w);
        *(float4*)(xs + r * 100 + c4 * 4) = v;
    }
    for (int idx = tid; idx < 96 * 24; idx += 512) {
        int n = idx / 24, k4 = idx % 24;
        float4 v = *(const float4*)(proj_w + (size_t)n * 96 + k4 * 4);
        v.x = tf32f(v.x); v.y = tf32f(v.y); v.z = tf32f(v.z); v.w = tf32f(v.w);
        *(float4*)(wsm + n * 100 + k4 * 4) = v;
    }
    __syncthreads();

    const int wq   = tid >> 5;
    const int lane = tid & 31;
    const int gid  = lane >> 2;
    const int t4   = lane & 3;
    const int mt   = wq & 7;
    const int nt0  = (wq >> 3) * 6;

    unsigned xa[12][4];
    {
        const float* x0 = xs + (mt * 16 + gid) * 100 + t4;
        const float* x1 = x0 + 8 * 100;
        #pragma unroll
        for (int ks = 0; ks < 12; ks++) {
            xa[ks][0] = __float_as_uint(x0[ks * 8]);
            xa[ks][1] = __float_as_uint(x1[ks * 8]);
            xa[ks][2] = __float_as_uint(x0[ks * 8 + 4]);
            xa[ks][3] = __float_as_uint(x1[ks * 8 + 4]);
        }
    }

    float accp[6][4];
    #pragma unroll
    for (int l = 0; l < 6; l++) {
        accp[l][0] = accp[l][1] = accp[l][2] = accp[l][3] = 0.f;
        const float* wr = wsm + ((nt0 + l) * 8 + gid) * 100 + t4;
        #pragma unroll
        for (int ks = 0; ks < 12; ks++) {
            unsigned wb[2];
            wb[0] = __float_as_uint(wr[ks * 8]);
            wb[1] = __float_as_uint(wr[ks * 8 + 4]);
            mma_tf32(accp[l], xa[ks], wb);
        }
    }
    __syncthreads();

    const int rloc = mt * 16 + gid;
    #pragma unroll
    for (int l = 0; l < 6; l++) {
        const int col = (nt0 + l) * 8 + t4 * 2;
        const float b0 = proj_b[col], b1 = proj_b[col + 1];
        *(float2*)(xs + rloc * 100 + col) =
            make_float2(accp[l][0] + b0, accp[l][1] + b1);
        *(float2*)(xs + (rloc + 8) * 100 + col) =
            make_float2(accp[l][2] + b0, accp[l][3] + b1);
    }
    __syncthreads();

    for (int i2 = tid; i2 < 128 * 24; i2 += 512) {
        const int r = i2 / 24, c4 = i2 % 24;
        float4 v = *(const float4*)(xs + r * 100 + c4 * 4);
        *(float4*)(out + (size_t)(m0 + r) * 96 + c4 * 4) = v;
    }
}

// ===========================================================================
extern "C" void kernel_launch(void* const* d_in, const int* in_sizes, int n_in,
                              void* d_out, int out_size)
{
    const float* x      = (const float*)d_in[0];
    const float* mask   = (const float*)d_in[1];
    const float* qkv_w  = (const float*)d_in[2];
    const float* qkv_b  = (const float*)d_in[3];
    const float* proj_w = (const float*)d_in[4];
    const float* proj_b = (const float*)d_in[5];
    float* out = (float*)d_out;

    const int smemQ = (128 * 100 + 288 * 100) * 4;                     // 166400
    const int smemA = (2 * 15552 + 3 * 96 * 24 + 3 * 96) * 4;          // 153216
    const int smemP = (128 * 100 + 96 * 100) * 4;                      // 89600

    cudaFuncSetAttribute(qkv_kernel,  cudaFuncAttributeMaxDynamicSharedMemorySize, smemQ);
    cudaFuncSetAttribute(attn_kernel, cudaFuncAttributeMaxDynamicSharedMemorySize, smemA);
    cudaFuncSetAttribute(proj_kernel, cudaFuncAttributeMaxDynamicSharedMemorySize, smemP);

    qkv_kernel<<<M_ROWS / 128, 512, smemQ>>>(x, qkv_w, qkv_b);
    attn_kernel<<<NSM, 576, smemA>>>(mask);
    proj_kernel<<<M_ROWS / 128, 512, smemP>>>(proj_w, proj_b, out);
}

// round 16
// speedup vs baseline: 3.3115x; 1.0042x over previous
#include <cuda_runtime.h>
#include <math.h>

#define B_WIN 1024
#define SEQ   288
#define CH    96
#define NH    4
#define HD    24
#define NW    128
#define M_ROWS (B_WIN * SEQ)   // 294912
#define NBH   (B_WIN * NH)     // 4096
#define NSM   148

// ---------------- tf32 mma helpers ----------------------------------------
__device__ __forceinline__ unsigned tf32_of(float f) {
    unsigned r; asm("cvt.rna.tf32.f32 %0, %1;" : "=r"(r) : "f"(f)); return r;
}
__device__ __forceinline__ float tf32f(float f) {
    return __uint_as_float(tf32_of(f));
}
__device__ __forceinline__ void mma_tf32(float* d, const unsigned* a, const unsigned* b) {
    asm volatile("mma.sync.aligned.m16n8k8.row.col.f32.tf32.tf32.f32 "
        "{%0,%1,%2,%3}, {%4,%5,%6,%7}, {%8,%9}, {%0,%1,%2,%3};"
        : "+f"(d[0]), "+f"(d[1]), "+f"(d[2]), "+f"(d[3])
        : "r"(a[0]), "r"(a[1]), "r"(a[2]), "r"(a[3]), "r"(b[0]), "r"(b[1]));
}
__device__ __forceinline__ unsigned smem_addr_u32(const void* p) {
    unsigned r;
    asm("{ .reg .u64 t; cvta.to.shared.u64 t, %1; cvt.u32.u64 %0, t; }"
        : "=r"(r) : "l"(p));
    return r;
}
__device__ __forceinline__ void bar_named(int id, int nthreads) {
    asm volatile("bar.sync %0, %1;" :: "r"(id), "r"(nthreads) : "memory");
}

// ---------------- scratch (device globals; no runtime allocation) ----------
__device__ float g_Q[B_WIN * NH * SEQ * HD];   // q pre-scaled, tf32-rounded
__device__ float g_K[B_WIN * NH * SEQ * HD];
__device__ float g_V[B_WIN * NH * SEQ * HD];
__device__ float g_O[M_ROWS * CH];

// ===========================================================================
// Kernel 1: QKV projection on tensor cores (tf32 mma).  R12 version (270us).
// ===========================================================================
__global__ __launch_bounds__(512) void qkv_kernel(
    const float* __restrict__ x,
    const float* __restrict__ qkv_w,
    const float* __restrict__ qkv_b)
{
    extern __shared__ float sm[];
    float* xs  = sm;               // [128][100]
    float* wsm = sm + 128 * 100;   // [288][100]

    const int tid = threadIdx.x;
    const int m0  = blockIdx.x * 128;

    for (int idx = tid; idx < 128 * 24; idx += 512) {
        int r = idx / 24, c4 = idx % 24;
        float4 v = *(const float4*)(x + (size_t)(m0 + r) * 96 + c4 * 4);
        v.x = tf32f(v.x); v.y = tf32f(v.y); v.z = tf32f(v.z); v.w = tf32f(v.w);
        *(float4*)(xs + r * 100 + c4 * 4) = v;
    }
    for (int idx = tid; idx < 288 * 24; idx += 512) {
        int n = idx / 24, k4 = idx % 24;
        float4 v = *(const float4*)(qkv_w + (size_t)n * 96 + k4 * 4);
        v.x = tf32f(v.x); v.y = tf32f(v.y); v.z = tf32f(v.z); v.w = tf32f(v.w);
        *(float4*)(wsm + n * 100 + k4 * 4) = v;
    }
    __syncthreads();

    const int wq   = tid >> 5;
    const int lane = tid & 31;
    const int gid  = lane >> 2;
    const int t4   = lane & 3;
    const int mt   = wq & 7;
    const int nt0  = (wq >> 3) * 18;
    const float scale = 0.20412414523193154f;

    unsigned xa[12][4];
    {
        const float* x0 = xs + (mt * 16 + gid) * 100 + t4;
        const float* x1 = x0 + 8 * 100;
        #pragma unroll
        for (int ks = 0; ks < 12; ks++) {
            xa[ks][0] = __float_as_uint(x0[ks * 8]);
            xa[ks][1] = __float_as_uint(x1[ks * 8]);
            xa[ks][2] = __float_as_uint(x0[ks * 8 + 4]);
            xa[ks][3] = __float_as_uint(x1[ks * 8 + 4]);
        }
    }

    const int ma = m0 + mt * 16 + gid;
    const int mb = ma + 8;
    const int ba = ma / SEQ, na = ma % SEQ;
    const int bb = mb / SEQ, nb = mb % SEQ;

    for (int nt = nt0; nt < nt0 + 18; ++nt) {
        float acc[4] = {0.f, 0.f, 0.f, 0.f};
        const float* wr = wsm + (nt * 8 + gid) * 100 + t4;
        #pragma unroll
        for (int ks = 0; ks < 12; ks++) {
            unsigned wb[2];
            wb[0] = __float_as_uint(wr[ks * 8]);
            wb[1] = __float_as_uint(wr[ks * 8 + 4]);
            mma_tf32(acc, xa[ks], wb);
        }
        const int col = nt * 8 + t4 * 2;
        const int s   = col / 96;
        const int within = col - s * 96;
        const int h   = within / 24;
        const int dd  = within - h * 24;
        float* dst = (s == 0) ? g_Q : (s == 1) ? g_K : g_V;
        const float b0 = qkv_b[col], b1 = qkv_b[col + 1];
        float2 va = make_float2(acc[0] + b0, acc[1] + b1);
        float2 vb = make_float2(acc[2] + b0, acc[3] + b1);
        if (s == 0) { va.x *= scale; va.y *= scale; vb.x *= scale; vb.y *= scale; }
        va.x = tf32f(va.x); va.y = tf32f(va.y);
        vb.x = tf32f(vb.x); vb.y = tf32f(vb.y);
        *(float2*)(dst + (((size_t)ba * NH + h) * SEQ + na) * HD + dd) = va;
        *(float2*)(dst + (((size_t)bb * NH + h) * SEQ + nb) * HD + dd) = vb;
    }
}

// ===========================================================================
// Kernel 2: persistent fused attention, double-buffered K/V via cp.async.
// grid = 148, block = 576 (18 warps).  warp = (mt 0..5, q 0..2).
// Deferred normalization: PV runs on unnormalized exp(P); writer divides by
// the total rowsum.  ONE named barrier per chunk (Pred/rowsum exchange,
// parity-double-buffered across chunks) + ONE full barrier per bh iter.
// smem: 2 x (Ks[288][28] + Vs[288][26]) + Pred[2][3][96][24] + rowsum[2][3][96]
//     = 182016 B.
// ===========================================================================
__device__ __forceinline__ void prefetch_kv(float* smbase, int buf, int bh, int tid)
{
    float* Ks = smbase + buf * 15552;
    float* Vs = Ks + 288 * 28;
    const size_t base = (size_t)bh * SEQ * HD;
    const float* gk = g_K + base;
    const float* gv = g_V + base;
    for (int i = tid; i < SEQ * 6; i += 576) {         // K: 16B ops
        int r = i / 6, c4 = i % 6;
        unsigned d = smem_addr_u32(Ks + r * 28 + c4 * 4);
        asm volatile("cp.async.ca.shared.global [%0], [%1], 16;"
                     :: "r"(d), "l"(gk + r * 24 + c4 * 4));
    }
    for (int i = tid; i < SEQ * 12; i += 576) {        // V: 8B ops
        int r = i / 12, c2 = i % 12;
        unsigned d = smem_addr_u32(Vs + r * 26 + c2 * 2);
        asm volatile("cp.async.ca.shared.global [%0], [%1], 8;"
                     :: "r"(d), "l"(gv + r * 24 + c2 * 2));
    }
}

__global__ __launch_bounds__(576) void attn_kernel(const float* __restrict__ mask)
{
    extern __shared__ float sm[];
    float* PredB  = sm + 2 * 15552;              // [2][3][96][24]
    float* rowsmB = PredB + 2 * 3 * 96 * 24;     // [2][3][96]

    const int tid  = threadIdx.x;
    const int wq   = tid >> 5;        // 0..17
    const int lane = tid & 31;
    const int gid  = lane >> 2;
    const int t4   = lane & 3;
    const int mt   = wq / 3;          // 0..5  (group)
    const int q    = wq % 3;          // col third
    const int c0   = q * 96;
    const int barid = 1 + mt;
    const int gtid  = q * 32 + lane;  // 0..95 within group

    const unsigned FULL = 0xffffffffu;
    const int srcA = (lane & ~3) | (t4 >> 1);
    const int srcB = srcA + 2;
    const bool odd = (t4 & 1);

    int bh  = blockIdx.x;
    int cur = 0;
    if (bh < NBH) {
        prefetch_kv(sm, 0, bh, tid);
        asm volatile("cp.async.commit_group;");
        asm volatile("cp.async.wait_group 0;");
    }
    __syncthreads();

    for (; bh < NBH; bh += NSM) {
        const int nbh = bh + NSM;
        if (nbh < NBH) {
            prefetch_kv(sm, cur ^ 1, nbh, tid);
            asm volatile("cp.async.commit_group;");
        }

        float* Ks = sm + cur * 15552;
        float* Vs = Ks + 288 * 28;
        const int b = bh >> 2;
        const int h = bh & 3;
        const int w = b & (NW - 1);
        const size_t base = (size_t)bh * SEQ * HD;

        for (int qc = 0; qc < 3; ++qc) {
            const int n0  = qc * 96;
            const int par = qc & 1;
            float* Pred   = PredB  + par * 6912;   // [3][96][24]
            float* rowsum = rowsmB + par * 288;    // [3][96]

            // ---- QK: 12 col-tiles, acc in registers --------------------
            unsigned qa[3][4];
            {
                const float* q0p = g_Q + base + (size_t)(n0 + mt * 16 + gid) * HD + t4;
                const float* q1p = q0p + 8 * HD;
                #pragma unroll
                for (int ks = 0; ks < 3; ks++) {
                    qa[ks][0] = __float_as_uint(q0p[ks * 8]);
                    qa[ks][1] = __float_as_uint(q1p[ks * 8]);
                    qa[ks][2] = __float_as_uint(q0p[ks * 8 + 4]);
                    qa[ks][3] = __float_as_uint(q1p[ks * 8 + 4]);
                }
            }
            float acc[12][4];
            #pragma unroll
            for (int j = 0; j < 12; j++) {
                acc[j][0] = acc[j][1] = acc[j][2] = acc[j][3] = 0.f;
                const float* kr = Ks + (c0 + j * 8 + gid) * 28 + t4;
                #pragma unroll
                for (int ks = 0; ks < 3; ks++) {
                    unsigned kb[2];
                    kb[0] = __float_as_uint(kr[ks * 8]);
                    kb[1] = __float_as_uint(kr[ks * 8 + 4]);
                    mma_tf32(acc[j], qa[ks], kb);
                }
            }

            // ---- mask + exp (unnormalized) -----------------------------
            const int rowa = n0 + mt * 16 + gid;
            const float* ma = mask + ((size_t)w * SEQ + rowa) * SEQ + c0;
            const float* mb = ma + 8 * SEQ;
            float sa = 0.f, sb = 0.f;
            #pragma unroll
            for (int j = 0; j < 12; j++) {
                const int cc = j * 8 + t4 * 2;
                float2 mva = *(const float2*)(ma + cc);
                float2 mvb = *(const float2*)(mb + cc);
                acc[j][0] = __expf(acc[j][0] + mva.x);
                acc[j][1] = __expf(acc[j][1] + mva.y);
                acc[j][2] = __expf(acc[j][2] + mvb.x);
                acc[j][3] = __expf(acc[j][3] + mvb.y);
                sa += acc[j][0] + acc[j][1];
                sb += acc[j][2] + acc[j][3];
            }
            sa += __shfl_xor_sync(FULL, sa, 1);
            sa += __shfl_xor_sync(FULL, sa, 2);
            sb += __shfl_xor_sync(FULL, sb, 1);
            sb += __shfl_xor_sync(FULL, sb, 2);
            if (t4 == 0) {
                rowsum[q * 96 + mt * 16 + gid]     = sa;
                rowsum[q * 96 + mt * 16 + 8 + gid] = sb;
            }

            // tf32-round unnormalized P (PV is scaled later in the writer)
            #pragma unroll
            for (int j = 0; j < 12; j++) {
                acc[j][0] = tf32f(acc[j][0]);
                acc[j][1] = tf32f(acc[j][1]);
                acc[j][2] = tf32f(acc[j][2]);
                acc[j][3] = tf32f(acc[j][3]);
            }

            // ---- O' = exp(P) V via shuffle c->a frag conversion --------
            float acc2[3][4];
            #pragma unroll
            for (int nt = 0; nt < 3; nt++)
                acc2[nt][0] = acc2[nt][1] = acc2[nt][2] = acc2[nt][3] = 0.f;

            #pragma unroll
            for (int j = 0; j < 12; j++) {
                float s0  = __shfl_sync(FULL, acc[j][0], srcA);
                float s1  = __shfl_sync(FULL, acc[j][1], srcA);
                float s2  = __shfl_sync(FULL, acc[j][2], srcA);
                float s3  = __shfl_sync(FULL, acc[j][3], srcA);
                float s0b = __shfl_sync(FULL, acc[j][0], srcB);
                float s1b = __shfl_sync(FULL, acc[j][1], srcB);
                float s2b = __shfl_sync(FULL, acc[j][2], srcB);
                float s3b = __shfl_sync(FULL, acc[j][3], srcB);
                unsigned pa[4];
                pa[0] = __float_as_uint(odd ? s1  : s0);
                pa[1] = __float_as_uint(odd ? s3  : s2);
                pa[2] = __float_as_uint(odd ? s1b : s0b);
                pa[3] = __float_as_uint(odd ? s3b : s2b);

                const int k0 = c0 + j * 8;
                #pragma unroll
                for (int nt = 0; nt < 3; nt++) {
                    unsigned vb[2];
                    vb[0] = __float_as_uint(Vs[(k0 + t4) * 26 + nt * 8 + gid]);
                    vb[1] = __float_as_uint(Vs[(k0 + 4 + t4) * 26 + nt * 8 + gid]);
                    mma_tf32(acc2[nt], pa, vb);
                }
            }
            {
                const int ra = mt * 16 + gid;
                float* pr = Pred + q * (96 * 24);
                #pragma unroll
                for (int nt = 0; nt < 3; nt++) {
                    const int cc = nt * 8 + t4 * 2;
                    *(float2*)(pr + ra * 24 + cc)       = make_float2(acc2[nt][0], acc2[nt][1]);
                    *(float2*)(pr + (ra + 8) * 24 + cc) = make_float2(acc2[nt][2], acc2[nt][3]);
                }
            }
            bar_named(barid, 96);   // group's Pred + rowsum complete

            // ---- group writer: 3-way reduce, divide by total rowsum ----
            #pragma unroll
            for (int e = gtid; e < 16 * 24; e += 96) {
                const int rl = e / 24, c = e % 24;
                const int ro = mt * 16 + rl;
                const float s = Pred[ro * 24 + c] + Pred[2304 + ro * 24 + c]
                              + Pred[4608 + ro * 24 + c];
                const float inv = 1.f / (rowsum[ro] + rowsum[96 + ro] + rowsum[192 + ro]);
                g_O[((size_t)b * SEQ + n0 + ro) * CH + h * HD + c] = s * inv;
            }
            // parity double-buffer + this chunk's named barrier order the
            // next same-parity reuse (chunk qc+2 / next-bh chunk 0 after the
            // full barrier below).
        }
        if (nbh < NBH) { asm volatile("cp.async.wait_group 0;"); }
        __syncthreads();   // buffer swap: all reads of cur done; next buffer visible
        cur ^= 1;
    }
}

// ===========================================================================
// Kernel 3: output projection on tensor cores, staged epilogue (~88us).
// ===========================================================================
__global__ __launch_bounds__(512) void proj_kernel(
    const float* __restrict__ proj_w,
    const float* __restrict__ proj_b,
    float* __restrict__ out)
{
    extern __shared__ float sm[];
    float* xs  = sm;               // [128][100]  (also the stage)
    float* wsm = sm + 128 * 100;   // [96][100]

    const int tid = threadIdx.x;
    const int m0  = blockIdx.x * 128;

    for (int idx = tid; idx < 128 * 24; idx += 512) {
        int r = idx / 24, c4 = idx % 24;
        float4 v = *(const float4*)(g_O + (size_t)(m0 + r) * 96 + c4 * 4);
        v.x = tf32f(v.x); v.y = tf32f(v.y); v.z = tf32f(v.z); v.w = tf32f(v.w);
        *(float4*)(xs + r * 100 + c4 * 4) = v;
    }
    for (int idx = tid; idx < 96 * 24; idx += 512) {
        int n = idx / 24, k4 = idx % 24;
        float4 v = *(const float4*)(proj_w + (size_t)n * 96 + k4 * 4);
        v.x = tf32f(v.x); v.y = tf32f(v.y); v.z = tf32f(v.z); v.w = tf32f(v.w);
        *(float4*)(wsm + n * 100 + k4 * 4) = v;
    }
    __syncthreads();

    const int wq   = tid >> 5;
    const int lane = tid & 31;
    const int gid  = lane >> 2;
    const int t4   = lane & 3;
    const int mt   = wq & 7;
    const int nt0  = (wq >> 3) * 6;

    unsigned xa[12][4];
    {
        const float* x0 = xs + (mt * 16 + gid) * 100 + t4;
        const float* x1 = x0 + 8 * 100;
        #pragma unroll
        for (int ks = 0; ks < 12; ks++) {
            xa[ks][0] = __float_as_uint(x0[ks * 8]);
            xa[ks][1] = __float_as_uint(x1[ks * 8]);
            xa[ks][2] = __float_as_uint(x0[ks * 8 + 4]);
            xa[ks][3] = __float_as_uint(x1[ks * 8 + 4]);
        }
    }

    float accp[6][4];
    #pragma unroll
    for (int l = 0; l < 6; l++) {
        accp[l][0] = accp[l][1] = accp[l][2] = accp[l][3] = 0.f;
        const float* wr = wsm + ((nt0 + l) * 8 + gid) * 100 + t4;
        #pragma unroll
        for (int ks = 0; ks < 12; ks++) {
            unsigned wb[2];
            wb[0] = __float_as_uint(wr[ks * 8]);
            wb[1] = __float_as_uint(wr[ks * 8 + 4]);
            mma_tf32(accp[l], xa[ks], wb);
        }
    }
    __syncthreads();

    const int rloc = mt * 16 + gid;
    #pragma unroll
    for (int l = 0; l < 6; l++) {
        const int col = (nt0 + l) * 8 + t4 * 2;
        const float b0 = proj_b[col], b1 = proj_b[col + 1];
        *(float2*)(xs + rloc * 100 + col) =
            make_float2(accp[l][0] + b0, accp[l][1] + b1);
        *(float2*)(xs + (rloc + 8) * 100 + col) =
            make_float2(accp[l][2] + b0, accp[l][3] + b1);
    }
    __syncthreads();

    for (int i2 = tid; i2 < 128 * 24; i2 += 512) {
        const int r = i2 / 24, c4 = i2 % 24;
        float4 v = *(const float4*)(xs + r * 100 + c4 * 4);
        *(float4*)(out + (size_t)(m0 + r) * 96 + c4 * 4) = v;
    }
}

// ===========================================================================
extern "C" void kernel_launch(void* const* d_in, const int* in_sizes, int n_in,
                              void* d_out, int out_size)
{
    const float* x      = (const float*)d_in[0];
    const float* mask   = (const float*)d_in[1];
    const float* qkv_w  = (const float*)d_in[2];
    const float* qkv_b  = (const float*)d_in[3];
    const float* proj_w = (const float*)d_in[4];
    const float* proj_b = (const float*)d_in[5];
    float* out = (float*)d_out;

    const int smemQ = (128 * 100 + 288 * 100) * 4;                       // 166400
    const int smemA = (2 * 15552 + 2 * 3 * 96 * 24 + 2 * 3 * 96) * 4;    // 182016
    const int smemP = (128 * 100 + 96 * 100) * 4;                        // 89600

    cudaFuncSetAttribute(qkv_kernel,  cudaFuncAttributeMaxDynamicSharedMemorySize, smemQ);
    cudaFuncSetAttribute(attn_kernel, cudaFuncAttributeMaxDynamicSharedMemorySize, smemA);
    cudaFuncSetAttribute(proj_kernel, cudaFuncAttributeMaxDynamicSharedMemorySize, smemP);

    qkv_kernel<<<M_ROWS / 128, 512, smemQ>>>(x, qkv_w, qkv_b);
    attn_kernel<<<NSM, 576, smemA>>>(mask);
    proj_kernel<<<M_ROWS / 128, 512, smemP>>>(proj_w, proj_b, out);
}

// round 17
// speedup vs baseline: 3.4187x; 1.0324x over previous
#include <cuda_runtime.h>
#include <math.h>

#define B_WIN 1024
#define SEQ   288
#define CH    96
#define NH    4
#define HD    24
#define NW    128
#define M_ROWS (B_WIN * SEQ)   // 294912
#define NBH   (B_WIN * NH)     // 4096
#define NSM   148

// ---------------- tf32 mma helpers ----------------------------------------
__device__ __forceinline__ unsigned tf32_of(float f) {
    unsigned r; asm("cvt.rna.tf32.f32 %0, %1;" : "=r"(r) : "f"(f)); return r;
}
__device__ __forceinline__ float tf32f(float f) {
    return __uint_as_float(tf32_of(f));
}
__device__ __forceinline__ void mma_tf32(float* d, const unsigned* a, const unsigned* b) {
    asm volatile("mma.sync.aligned.m16n8k8.row.col.f32.tf32.tf32.f32 "
        "{%0,%1,%2,%3}, {%4,%5,%6,%7}, {%8,%9}, {%0,%1,%2,%3};"
        : "+f"(d[0]), "+f"(d[1]), "+f"(d[2]), "+f"(d[3])
        : "r"(a[0]), "r"(a[1]), "r"(a[2]), "r"(a[3]), "r"(b[0]), "r"(b[1]));
}
__device__ __forceinline__ unsigned smem_addr_u32(const void* p) {
    unsigned r;
    asm("{ .reg .u64 t; cvta.to.shared.u64 t, %1; cvt.u32.u64 %0, t; }"
        : "=r"(r) : "l"(p));
    return r;
}
__device__ __forceinline__ void bar_named(int id, int nthreads) {
    asm volatile("bar.sync %0, %1;" :: "r"(id), "r"(nthreads) : "memory");
}

// ---------------- scratch (device globals; no runtime allocation) ----------
__device__ float g_Q[B_WIN * NH * SEQ * HD];   // q pre-scaled, tf32-rounded
__device__ float g_K[B_WIN * NH * SEQ * HD];
__device__ float g_V[B_WIN * NH * SEQ * HD];
__device__ float g_O[M_ROWS * CH];

// ===========================================================================
// Kernel 1: QKV projection on tensor cores (tf32 mma), 4 subtiles/block.
// grid = M/512 = 576, block = 512 (16 warps).  W filled ONCE per block;
// per subtile: fill xs -> bar -> load xa -> bar -> mma + direct epilogue.
// ===========================================================================
__global__ __launch_bounds__(512) void qkv_kernel(
    const float* __restrict__ x,
    const float* __restrict__ qkv_w,
    const float* __restrict__ qkv_b)
{
    extern __shared__ float sm[];
    float* xs  = sm;               // [128][100]
    float* wsm = sm + 128 * 100;   // [288][100]

    const int tid = threadIdx.x;
    const int mb0 = blockIdx.x * 512;

    for (int idx = tid; idx < 288 * 24; idx += 512) {
        int n = idx / 24, k4 = idx % 24;
        float4 v = *(const float4*)(qkv_w + (size_t)n * 96 + k4 * 4);
        v.x = tf32f(v.x); v.y = tf32f(v.y); v.z = tf32f(v.z); v.w = tf32f(v.w);
        *(float4*)(wsm + n * 100 + k4 * 4) = v;
    }

    const int wq   = tid >> 5;
    const int lane = tid & 31;
    const int gid  = lane >> 2;
    const int t4   = lane & 3;
    const int mt   = wq & 7;
    const int nt0  = (wq >> 3) * 18;
    const float scale = 0.20412414523193154f;

    for (int t = 0; t < 4; ++t) {
        const int m0 = mb0 + t * 128;

        for (int idx = tid; idx < 128 * 24; idx += 512) {
            int r = idx / 24, c4 = idx % 24;
            float4 v = *(const float4*)(x + (size_t)(m0 + r) * 96 + c4 * 4);
            v.x = tf32f(v.x); v.y = tf32f(v.y); v.z = tf32f(v.z); v.w = tf32f(v.w);
            *(float4*)(xs + r * 100 + c4 * 4) = v;
        }
        __syncthreads();   // xs (and, first iter, wsm) ready

        unsigned xa[12][4];
        {
            const float* x0 = xs + (mt * 16 + gid) * 100 + t4;
            const float* x1 = x0 + 8 * 100;
            #pragma unroll
            for (int ks = 0; ks < 12; ks++) {
                xa[ks][0] = __float_as_uint(x0[ks * 8]);
                xa[ks][1] = __float_as_uint(x1[ks * 8]);
                xa[ks][2] = __float_as_uint(x0[ks * 8 + 4]);
                xa[ks][3] = __float_as_uint(x1[ks * 8 + 4]);
            }
        }
        __syncthreads();   // xa loads done; next subtile may overwrite xs

        const int ma = m0 + mt * 16 + gid;
        const int mbr = ma + 8;
        const int ba = ma / SEQ, na = ma % SEQ;
        const int bb = mbr / SEQ, nb = mbr % SEQ;

        for (int nt = nt0; nt < nt0 + 18; ++nt) {
            float acc[4] = {0.f, 0.f, 0.f, 0.f};
            const float* wr = wsm + (nt * 8 + gid) * 100 + t4;
            #pragma unroll
            for (int ks = 0; ks < 12; ks++) {
                unsigned wb[2];
                wb[0] = __float_as_uint(wr[ks * 8]);
                wb[1] = __float_as_uint(wr[ks * 8 + 4]);
                mma_tf32(acc, xa[ks], wb);
            }
            const int col = nt * 8 + t4 * 2;
            const int s   = col / 96;
            const int within = col - s * 96;
            const int h   = within / 24;
            const int dd  = within - h * 24;
            float* dst = (s == 0) ? g_Q : (s == 1) ? g_K : g_V;
            const float b0 = qkv_b[col], b1 = qkv_b[col + 1];
            float2 va = make_float2(acc[0] + b0, acc[1] + b1);
            float2 vb = make_float2(acc[2] + b0, acc[3] + b1);
            if (s == 0) { va.x *= scale; va.y *= scale; vb.x *= scale; vb.y *= scale; }
            va.x = tf32f(va.x); va.y = tf32f(va.y);
            vb.x = tf32f(vb.x); vb.y = tf32f(vb.y);
            *(float2*)(dst + (((size_t)ba * NH + h) * SEQ + na) * HD + dd) = va;
            *(float2*)(dst + (((size_t)bb * NH + h) * SEQ + nb) * HD + dd) = vb;
        }
    }
}

// ===========================================================================
// Kernel 2: persistent fused attention, double-buffered K/V via cp.async.
// grid = 148, block = 576 (18 warps).  warp = (mt 0..5, q 0..2).
// Deferred normalization; P fed to PV mma UNROUNDED (HW tf32 truncation).
// ONE named barrier per chunk + ONE full barrier per bh iter.
// smem: 2 x (Ks[288][28] + Vs[288][26]) + Pred[2][3][96][24] + rowsum[2][3][96]
//     = 182016 B.
// ===========================================================================
__device__ __forceinline__ void prefetch_kv(float* smbase, int buf, int bh, int tid)
{
    float* Ks = smbase + buf * 15552;
    float* Vs = Ks + 288 * 28;
    const size_t base = (size_t)bh * SEQ * HD;
    const float* gk = g_K + base;
    const float* gv = g_V + base;
    for (int i = tid; i < SEQ * 6; i += 576) {         // K: 16B ops
        int r = i / 6, c4 = i % 6;
        unsigned d = smem_addr_u32(Ks + r * 28 + c4 * 4);
        asm volatile("cp.async.ca.shared.global [%0], [%1], 16;"
                     :: "r"(d), "l"(gk + r * 24 + c4 * 4));
    }
    for (int i = tid; i < SEQ * 12; i += 576) {        // V: 8B ops
        int r = i / 12, c2 = i % 12;
        unsigned d = smem_addr_u32(Vs + r * 26 + c2 * 2);
        asm volatile("cp.async.ca.shared.global [%0], [%1], 8;"
                     :: "r"(d), "l"(gv + r * 24 + c2 * 2));
    }
}

__global__ __launch_bounds__(576) void attn_kernel(const float* __restrict__ mask)
{
    extern __shared__ float sm[];
    float* PredB  = sm + 2 * 15552;              // [2][3][96][24]
    float* rowsmB = PredB + 2 * 3 * 96 * 24;     // [2][3][96]

    const int tid  = threadIdx.x;
    const int wq   = tid >> 5;        // 0..17
    const int lane = tid & 31;
    const int gid  = lane >> 2;
    const int t4   = lane & 3;
    const int mt   = wq / 3;          // 0..5  (group)
    const int q    = wq % 3;          // col third
    const int c0   = q * 96;
    const int barid = 1 + mt;
    const int gtid  = q * 32 + lane;  // 0..95 within group

    const unsigned FULL = 0xffffffffu;
    const int srcA = (lane & ~3) | (t4 >> 1);
    const int srcB = srcA + 2;
    const bool odd = (t4 & 1);

    int bh  = blockIdx.x;
    int cur = 0;
    if (bh < NBH) {
        prefetch_kv(sm, 0, bh, tid);
        asm volatile("cp.async.commit_group;");
        asm volatile("cp.async.wait_group 0;");
    }
    __syncthreads();

    for (; bh < NBH; bh += NSM) {
        const int nbh = bh + NSM;
        if (nbh < NBH) {
            prefetch_kv(sm, cur ^ 1, nbh, tid);
            asm volatile("cp.async.commit_group;");
        }

        float* Ks = sm + cur * 15552;
        float* Vs = Ks + 288 * 28;
        const int b = bh >> 2;
        const int h = bh & 3;
        const int w = b & (NW - 1);
        const size_t base = (size_t)bh * SEQ * HD;

        for (int qc = 0; qc < 3; ++qc) {
            const int n0  = qc * 96;
            const int par = qc & 1;
            float* Pred   = PredB  + par * 6912;   // [3][96][24]
            float* rowsum = rowsmB + par * 288;    // [3][96]

            // ---- QK: 12 col-tiles, acc in registers --------------------
            unsigned qa[3][4];
            {
                const float* q0p = g_Q + base + (size_t)(n0 + mt * 16 + gid) * HD + t4;
                const float* q1p = q0p + 8 * HD;
                #pragma unroll
                for (int ks = 0; ks < 3; ks++) {
                    qa[ks][0] = __float_as_uint(q0p[ks * 8]);
                    qa[ks][1] = __float_as_uint(q1p[ks * 8]);
                    qa[ks][2] = __float_as_uint(q0p[ks * 8 + 4]);
                    qa[ks][3] = __float_as_uint(q1p[ks * 8 + 4]);
                }
            }
            float acc[12][4];
            #pragma unroll
            for (int j = 0; j < 12; j++) {
                acc[j][0] = acc[j][1] = acc[j][2] = acc[j][3] = 0.f;
                const float* kr = Ks + (c0 + j * 8 + gid) * 28 + t4;
                #pragma unroll
                for (int ks = 0; ks < 3; ks++) {
                    unsigned kb[2];
                    kb[0] = __float_as_uint(kr[ks * 8]);
                    kb[1] = __float_as_uint(kr[ks * 8 + 4]);
                    mma_tf32(acc[j], qa[ks], kb);
                }
            }

            // ---- mask + exp (unnormalized) -----------------------------
            const int rowa = n0 + mt * 16 + gid;
            const float* ma = mask + ((size_t)w * SEQ + rowa) * SEQ + c0;
            const float* mb = ma + 8 * SEQ;
            float sa = 0.f, sb = 0.f;
            #pragma unroll
            for (int j = 0; j < 12; j++) {
                const int cc = j * 8 + t4 * 2;
                float2 mva = *(const float2*)(ma + cc);
                float2 mvb = *(const float2*)(mb + cc);
                acc[j][0] = __expf(acc[j][0] + mva.x);
                acc[j][1] = __expf(acc[j][1] + mva.y);
                acc[j][2] = __expf(acc[j][2] + mvb.x);
                acc[j][3] = __expf(acc[j][3] + mvb.y);
                sa += acc[j][0] + acc[j][1];
                sb += acc[j][2] + acc[j][3];
            }
            sa += __shfl_xor_sync(FULL, sa, 1);
            sa += __shfl_xor_sync(FULL, sa, 2);
            sb += __shfl_xor_sync(FULL, sb, 1);
            sb += __shfl_xor_sync(FULL, sb, 2);
            if (t4 == 0) {
                rowsum[q * 96 + mt * 16 + gid]     = sa;
                rowsum[q * 96 + mt * 16 + 8 + gid] = sb;
            }

            // ---- O' = exp(P) V via shuffle c->a frag conversion --------
            // (P fed unrounded: tf32 HMMA truncates mantissa in hardware)
            float acc2[3][4];
            #pragma unroll
            for (int nt = 0; nt < 3; nt++)
                acc2[nt][0] = acc2[nt][1] = acc2[nt][2] = acc2[nt][3] = 0.f;

            #pragma unroll
            for (int j = 0; j < 12; j++) {
                float s0  = __shfl_sync(FULL, acc[j][0], srcA);
                float s1  = __shfl_sync(FULL, acc[j][1], srcA);
                float s2  = __shfl_sync(FULL, acc[j][2], srcA);
                float s3  = __shfl_sync(FULL, acc[j][3], srcA);
                float s0b = __shfl_sync(FULL, acc[j][0], srcB);
                float s1b = __shfl_sync(FULL, acc[j][1], srcB);
                float s2b = __shfl_sync(FULL, acc[j][2], srcB);
                float s3b = __shfl_sync(FULL, acc[j][3], srcB);
                unsigned pa[4];
                pa[0] = __float_as_uint(odd ? s1  : s0);
                pa[1] = __float_as_uint(odd ? s3  : s2);
                pa[2] = __float_as_uint(odd ? s1b : s0b);
                pa[3] = __float_as_uint(odd ? s3b : s2b);

                const int k0 = c0 + j * 8;
                #pragma unroll
                for (int nt = 0; nt < 3; nt++) {
                    unsigned vb[2];
                    vb[0] = __float_as_uint(Vs[(k0 + t4) * 26 + nt * 8 + gid]);
                    vb[1] = __float_as_uint(Vs[(k0 + 4 + t4) * 26 + nt * 8 + gid]);
                    mma_tf32(acc2[nt], pa, vb);
                }
            }
            {
                const int ra = mt * 16 + gid;
                float* pr = Pred + q * (96 * 24);
                #pragma unroll
                for (int nt = 0; nt < 3; nt++) {
                    const int cc = nt * 8 + t4 * 2;
                    *(float2*)(pr + ra * 24 + cc)       = make_float2(acc2[nt][0], acc2[nt][1]);
                    *(float2*)(pr + (ra + 8) * 24 + cc) = make_float2(acc2[nt][2], acc2[nt][3]);
                }
            }
            bar_named(barid, 96);   // group's Pred + rowsum complete

            // ---- group writer: 3-way reduce, divide by total rowsum ----
            #pragma unroll
            for (int e = gtid; e < 16 * 24; e += 96) {
                const int rl = e / 24, c = e % 24;
                const int ro = mt * 16 + rl;
                const float s = Pred[ro * 24 + c] + Pred[2304 + ro * 24 + c]
                              + Pred[4608 + ro * 24 + c];
                const float inv = 1.f / (rowsum[ro] + rowsum[96 + ro] + rowsum[192 + ro]);
                g_O[((size_t)b * SEQ + n0 + ro) * CH + h * HD + c] = s * inv;
            }
        }
        if (nbh < NBH) { asm volatile("cp.async.wait_group 0;"); }
        __syncthreads();   // buffer swap: all reads of cur done; next buffer visible
        cur ^= 1;
    }
}

// ===========================================================================
// Kernel 3: output projection on tensor cores, staged epilogue (~88us).
// ===========================================================================
__global__ __launch_bounds__(512) void proj_kernel(
    const float* __restrict__ proj_w,
    const float* __restrict__ proj_b,
    float* __restrict__ out)
{
    extern __shared__ float sm[];
    float* xs  = sm;               // [128][100]  (also the stage)
    float* wsm = sm + 128 * 100;   // [96][100]

    const int tid = threadIdx.x;
    const int m0  = blockIdx.x * 128;

    for (int idx = tid; idx < 128 * 24; idx += 512) {
        int r = idx / 24, c4 = idx % 24;
        float4 v = *(const float4*)(g_O + (size_t)(m0 + r) * 96 + c4 * 4);
        v.x = tf32f(v.x); v.y = tf32f(v.y); v.z = tf32f(v.z); v.w = tf32f(v.w);
        *(float4*)(xs + r * 100 + c4 * 4) = v;
    }
    for (int idx = tid; idx < 96 * 24; idx += 512) {
        int n = idx / 24, k4 = idx % 24;
        float4 v = *(const float4*)(proj_w + (size_t)n * 96 + k4 * 4);
        v.x = tf32f(v.x); v.y = tf32f(v.y); v.z = tf32f(v.z); v.w = tf32f(v.w);
        *(float4*)(wsm + n * 100 + k4 * 4) = v;
    }
    __syncthreads();

    const int wq   = tid >> 5;
    const int lane = tid & 31;
    const int gid  = lane >> 2;
    const int t4   = lane & 3;
    const int mt   = wq & 7;
    const int nt0  = (wq >> 3) * 6;

    unsigned xa[12][4];
    {
        const float* x0 = xs + (mt * 16 + gid) * 100 + t4;
        const float* x1 = x0 + 8 * 100;
        #pragma unroll
        for (int ks = 0; ks < 12; ks++) {
            xa[ks][0] = __float_as_uint(x0[ks * 8]);
            xa[ks][1] = __float_as_uint(x1[ks * 8]);
            xa[ks][2] = __float_as_uint(x0[ks * 8 + 4]);
            xa[ks][3] = __float_as_uint(x1[ks * 8 + 4]);
        }
    }

    float accp[6][4];
    #pragma unroll
    for (int l = 0; l < 6; l++) {
        accp[l][0] = accp[l][1] = accp[l][2] = accp[l][3] = 0.f;
        const float* wr = wsm + ((nt0 + l) * 8 + gid) * 100 + t4;
        #pragma unroll
        for (int ks = 0; ks < 12; ks++) {
            unsigned wb[2];
            wb[0] = __float_as_uint(wr[ks * 8]);
            wb[1] = __float_as_uint(wr[ks * 8 + 4]);
            mma_tf32(accp[l], xa[ks], wb);
        }
    }
    __syncthreads();

    const int rloc = mt * 16 + gid;
    #pragma unroll
    for (int l = 0; l < 6; l++) {
        const int col = (nt0 + l) * 8 + t4 * 2;
        const float b0 = proj_b[col], b1 = proj_b[col + 1];
        *(float2*)(xs + rloc * 100 + col) =
            make_float2(accp[l][0] + b0, accp[l][1] + b1);
        *(float2*)(xs + (rloc + 8) * 100 + col) =
            make_float2(accp[l][2] + b0, accp[l][3] + b1);
    }
    __syncthreads();

    for (int i2 = tid; i2 < 128 * 24; i2 += 512) {
        const int r = i2 / 24, c4 = i2 % 24;
        float4 v = *(const float4*)(xs + r * 100 + c4 * 4);
        *(float4*)(out + (size_t)(m0 + r) * 96 + c4 * 4) = v;
    }
}

// ===========================================================================
extern "C" void kernel_launch(void* const* d_in, const int* in_sizes, int n_in,
                              void* d_out, int out_size)
{
    const float* x      = (const float*)d_in[0];
    const float* mask   = (const float*)d_in[1];
    const float* qkv_w  = (const float*)d_in[2];
    const float* qkv_b  = (const float*)d_in[3];
    const float* proj_w = (const float*)d_in[4];
    const float* proj_b = (const float*)d_in[5];
    float* out = (float*)d_out;

    const int smemQ = (128 * 100 + 288 * 100) * 4;                       // 166400
    const int smemA = (2 * 15552 + 2 * 3 * 96 * 24 + 2 * 3 * 96) * 4;    // 182016
    const int smemP = (128 * 100 + 96 * 100) * 4;                        // 89600

    cudaFuncSetAttribute(qkv_kernel,  cudaFuncAttributeMaxDynamicSharedMemorySize, smemQ);
    cudaFuncSetAttribute(attn_kernel, cudaFuncAttributeMaxDynamicSharedMemorySize, smemA);
    cudaFuncSetAttribute(proj_kernel, cudaFuncAttributeMaxDynamicSharedMemorySize, smemP);

    qkv_kernel<<<M_ROWS / 512, 512, smemQ>>>(x, qkv_w, qkv_b);
    attn_kernel<<<NSM, 576, smemA>>>(mask);
    proj_kernel<<<M_ROWS / 128, 512, smemP>>>(proj_w, proj_b, out);
}